// round 13
// baseline (speedup 1.0000x reference)
#include <cuda_runtime.h>
#include <math.h>

// Problem constants: B=8, NQ=NK=1024, D=512, H=8, dh=64
#define BATCH 8
#define NQ 1024
#define NK 1024
#define DIM 512
#define HEADS 8
#define DH 64
#define BH (BATCH*HEADS)          // 64
#define MROWS (BATCH*NQ)          // 8192

// ---------------- scratch ----------------
__device__ float g_q[BH * NK * DH];   // full rows, f32
__device__ float g_k[BH * NK * DH];   // COMPACTED rows, tf32-rounded
__device__ float g_v[BH * NK * DH];   // COMPACTED rows, tf32-rounded
__device__ float g_O[MROWS * DIM];
__device__ float g_U[MROWS * DIM];
__device__ float g_mu[MROWS];
__device__ float g_rs[MROWS];
__device__ float g_part[HEADS][MROWS][2];   // [head][row] LN0 partials (coalesced)
__device__ int   g_idx[BATCH * NK];
__device__ int   g_cnt[BATCH];

// ---------------- helpers ----------------
__device__ __forceinline__ unsigned f2tf(float x) {
    unsigned u;
    asm("cvt.rna.tf32.f32 %0, %1;" : "=r"(u) : "f"(x));
    return u;
}

__device__ __forceinline__ void mma_tf32(float c[4],
                                         unsigned a0, unsigned a1, unsigned a2, unsigned a3,
                                         unsigned b0, unsigned b1)
{
    asm volatile(
        "mma.sync.aligned.m16n8k8.row.col.f32.tf32.tf32.f32 "
        "{%0,%1,%2,%3}, {%4,%5,%6,%7}, {%8,%9}, {%0,%1,%2,%3};\n"
        : "+f"(c[0]), "+f"(c[1]), "+f"(c[2]), "+f"(c[3])
        : "r"(a0), "r"(a1), "r"(a2), "r"(a3), "r"(b0), "r"(b1));
}

__device__ __forceinline__ void cp16(unsigned smem_addr, const void* gptr, int src_sz) {
    asm volatile("cp.async.cg.shared.global [%0], [%1], 16, %2;\n"
                 :: "r"(smem_addr), "l"(gptr), "r"(src_sz));
}
__device__ __forceinline__ void cp16f(unsigned smem_addr, const void* gptr) {
    asm volatile("cp.async.cg.shared.global [%0], [%1], 16;\n"
                 :: "r"(smem_addr), "l"(gptr));
}

__device__ __forceinline__ unsigned smem_cast(const void* p) {
    unsigned long long q;
    asm("cvta.to.shared.u64 %0, %1;" : "=l"(q) : "l"(p));
    return (unsigned)q;
}

// ---------------- mask compaction ----------------
__global__ void compact_mask(const int* __restrict__ mask)
{
    __shared__ int warpsums[32];
    const int b = blockIdx.x, t = threadIdx.x;
    const int lane = t & 31, warp = t >> 5;
    int m = (mask[b * 1024 + t] != 0) ? 1 : 0;
    unsigned bal = __ballot_sync(0xffffffffu, m);
    int pre = __popc(bal & ((1u << lane) - 1u));
    if (lane == 0) warpsums[warp] = __popc(bal);
    __syncthreads();
    if (warp == 0) {
        int v = warpsums[lane];
        #pragma unroll
        for (int o = 1; o < 32; o <<= 1) {
            int u = __shfl_up_sync(0xffffffffu, v, o);
            if (lane >= o) v += u;
        }
        warpsums[lane] = v;
    }
    __syncthreads();
    int base = (warp == 0) ? 0 : warpsums[warp - 1];
    if (m) g_idx[b * 1024 + base + pre] = t;
    if (t == 1023) g_cnt[b] = warpsums[31];
}

// ---------------- 128x128 tensor-core GEMM (4-stage cp.async) --------------
#define ASTRIDE 20
#define BSTRIDE 132
#define GSTAGES 4
#define GEMM_SMEM ((GSTAGES*128*ASTRIDE + GSTAGES*16*BSTRIDE) * 4)
template<int MODE>
__global__ void __launch_bounds__(256, 2) gemm128(
    const float* __restrict__ p0, const float* __restrict__ p1,
    const float* __restrict__ p2, const float* __restrict__ p3,
    const float* __restrict__ p4, const float* __restrict__ p5,
    const float* __restrict__ p6, const float* __restrict__ p7)
{
    extern __shared__ float smg[];
    float (*As)[128][ASTRIDE] = (float(*)[128][ASTRIDE])smg;
    float (*Bs)[16][BSTRIDE]  = (float(*)[16][BSTRIDE])(smg + GSTAGES*128*ASTRIDE);
    const int z = blockIdx.z;
    const int n0 = blockIdx.x * 128;
    const int bb = blockIdx.y >> 3;
    const int tyl = blockIdx.y & 7;
    const int m0 = blockIdx.y * 128;

    const float* A; const float* W; const float* bias; float* outp;
    const float* gamma = p4; const float* beta = p5;
    if (MODE == 0) {
        A    = (z == 0) ? p0 : p1;
        W    = (z == 0) ? p2 : (z == 1) ? p4 : p6;
        bias = (z == 0) ? p3 : (z == 1) ? p5 : p7;
        outp = (z == 0) ? g_q : (z == 1) ? g_k : g_v;
    } else {
        A = (const float*)g_O; W = p2; bias = p3; outp = g_U;
    }

    int cnt = 1024;
    if (MODE == 0 && z > 0) {
        cnt = g_cnt[bb];
        if (tyl * 128 >= cnt) return;
    }

    const int tid = threadIdx.x;
    const int warp = tid >> 5, lane = tid & 31;
    const int wm = warp >> 2, wn = warp & 3;
    const int g = lane >> 2, t = lane & 3;
    const int mbase = wm * 64;
    const int nbase = wn * 32;

    const unsigned sA = smem_cast(smg);
    const unsigned sB = sA + (unsigned)(GSTAGES*128*ASTRIDE) * 4;

    const int r1 = tid >> 2;
    const int c4 = (tid & 3) << 2;
    const float* arow1; const float* arow2;
    float mu1 = 0.f, rs1 = 0.f, mu2 = 0.f, rs2 = 0.f;
    {
        int li1 = tyl * 128 + r1;
        int li2 = li1 + 64;
        if (MODE == 0 && z > 0) {
            int gi1 = (li1 < cnt) ? g_idx[bb * 1024 + li1] : 0;
            int gi2 = (li2 < cnt) ? g_idx[bb * 1024 + li2] : 0;
            arow1 = A + ((size_t)bb * 1024 + gi1) * 512;
            arow2 = A + ((size_t)bb * 1024 + gi2) * 512;
        } else {
            arow1 = A + ((size_t)bb * 1024 + li1) * 512;
            arow2 = A + ((size_t)bb * 1024 + li2) * 512;
        }
        if (MODE == 1) {
            mu1 = g_mu[m0 + r1];      rs1 = g_rs[m0 + r1];
            mu2 = g_mu[m0 + r1 + 64]; rs2 = g_rs[m0 + r1 + 64];
        }
    }

    auto loadAB = [&](int k0, int bufi) {
        unsigned abase = sA + (unsigned)(bufi * 128 * ASTRIDE) * 4;
        if (MODE == 0) {
            cp16f(abase + (unsigned)((r1      ) * ASTRIDE + c4) * 4, arow1 + k0 + c4);
            cp16f(abase + (unsigned)((r1 + 64 ) * ASTRIDE + c4) * 4, arow2 + k0 + c4);
        } else {
            float4 a1 = *(const float4*)(arow1 + k0 + c4);
            float4 a2 = *(const float4*)(arow2 + k0 + c4);
            float4 gm = *(const float4*)(gamma + k0 + c4);
            float4 bt = *(const float4*)(beta  + k0 + c4);
            a1.x = (a1.x - mu1) * rs1 * gm.x + bt.x;
            a1.y = (a1.y - mu1) * rs1 * gm.y + bt.y;
            a1.z = (a1.z - mu1) * rs1 * gm.z + bt.z;
            a1.w = (a1.w - mu1) * rs1 * gm.w + bt.w;
            a2.x = (a2.x - mu2) * rs2 * gm.x + bt.x;
            a2.y = (a2.y - mu2) * rs2 * gm.y + bt.y;
            a2.z = (a2.z - mu2) * rs2 * gm.z + bt.z;
            a2.w = (a2.w - mu2) * rs2 * gm.w + bt.w;
            uint4 u1 = make_uint4(f2tf(a1.x), f2tf(a1.y), f2tf(a1.z), f2tf(a1.w));
            uint4 u2 = make_uint4(f2tf(a2.x), f2tf(a2.y), f2tf(a2.z), f2tf(a2.w));
            *(uint4*)&As[bufi][r1     ][c4] = u1;
            *(uint4*)&As[bufi][r1 + 64][c4] = u2;
        }
        unsigned bbase = sB + (unsigned)(bufi * 16 * BSTRIDE) * 4;
        #pragma unroll
        for (int it = 0; it < 2; it++) {
            int idx = tid + it * 256;
            int r = idx >> 5, cc = (idx & 31) << 2;
            cp16f(bbase + (unsigned)(r * BSTRIDE + cc) * 4,
                  W + (size_t)(k0 + r) * 512 + n0 + cc);
        }
        asm volatile("cp.async.commit_group;\n");
    };

    float acc[4][4][4];
    #pragma unroll
    for (int i = 0; i < 4; i++)
        #pragma unroll
        for (int j = 0; j < 4; j++)
            #pragma unroll
            for (int q = 0; q < 4; q++) acc[i][j][q] = 0.f;

    loadAB(0, 0);
    loadAB(16, 1);

    for (int it = 0; it < 32; it++) {
        int cur = it & 3;
        if (it + 2 < 32) loadAB((it + 2) * 16, (it + 2) & 3);
        else asm volatile("cp.async.commit_group;\n");
        asm volatile("cp.async.wait_group 2;\n");
        __syncthreads();

        const unsigned* Ab = (const unsigned*)As[cur];
        const unsigned* Bb = (const unsigned*)Bs[cur];
        #pragma unroll
        for (int ks = 0; ks < 2; ks++) {
            int kk = ks * 8;
            unsigned av[4][4], bv[4][2];
            #pragma unroll
            for (int i = 0; i < 4; i++) {
                int mb = mbase + i * 16;
                av[i][0] = Ab[(mb + g    ) * ASTRIDE + kk + t    ];
                av[i][1] = Ab[(mb + g + 8) * ASTRIDE + kk + t    ];
                av[i][2] = Ab[(mb + g    ) * ASTRIDE + kk + t + 4];
                av[i][3] = Ab[(mb + g + 8) * ASTRIDE + kk + t + 4];
            }
            #pragma unroll
            for (int j = 0; j < 4; j++) {
                bv[j][0] = Bb[(kk + t    ) * BSTRIDE + nbase + j * 8 + g];
                bv[j][1] = Bb[(kk + t + 4) * BSTRIDE + nbase + j * 8 + g];
            }
            #pragma unroll
            for (int i = 0; i < 4; i++)
                #pragma unroll
                for (int j = 0; j < 4; j++)
                    mma_tf32(acc[i][j], av[i][0], av[i][1], av[i][2], av[i][3],
                             bv[j][0], bv[j][1]);
        }
    }

    #pragma unroll
    for (int i = 0; i < 4; i++) {
        int lr0 = mbase + i * 16 + g;
        #pragma unroll
        for (int j = 0; j < 4; j++) {
            int c0 = n0 + nbase + j * 8 + 2 * t;
            #pragma unroll
            for (int q = 0; q < 4; q++) {
                int lr = lr0 + (q >> 1) * 8;
                int c  = c0 + (q & 1);
                float val = acc[i][j][q] + bias[c];
                if (MODE == 0) {
                    int n = tyl * 128 + lr;
                    int h = c >> 6, d = c & 63;
                    float sval = (z == 0) ? val : __uint_as_float(f2tf(val));
                    outp[(((size_t)(bb * HEADS + h)) * 1024 + n) * 64 + d] = sval;
                } else {
                    int r = m0 + lr;
                    float xv = (g_O[(size_t)r * 512 + c] - g_mu[r]) * g_rs[r]
                               * gamma[c] + beta[c];
                    outp[(size_t)r * 512 + c] = xv + fmaxf(val, 0.f);
                }
            }
        }
    }
}

// ---------------- fused flash attention (no-max softmax) -------------------
// Scores bounded (|s| < ~1 for this problem's scale): softmax computed as
// exp(s)/sum(exp(s)) directly -- no running max, no O rescale.
#define KSTRIDE 68
#define VSTRIDE 72
#define FSTAGES 4
#define KS_OFF 0
#define VS_OFF (FSTAGES*32*KSTRIDE)
#define PS_OFF (VS_OFF + FSTAGES*32*VSTRIDE)
#define SMEM_FLASH ((PS_OFF + 8*32*24) * 4)

__global__ void __launch_bounds__(256) flash_attn()
{
    extern __shared__ unsigned sm[];
    const unsigned smem_u32 = smem_cast(sm);

    const int bh = blockIdx.y;
    const int b = bh >> 3, h = bh & 7;
    const int i0 = blockIdx.x * 128;
    const int tid = threadIdx.x;
    const int warp = tid >> 5, lane = tid & 31;
    const int g = lane >> 2, t = lane & 3;

    const int nk = g_cnt[b];
    const int nchunks = (nk + 31) >> 5;
    const float* kbase = g_k + (size_t)bh * 1024 * 64;
    const float* vbase = g_v + (size_t)bh * 1024 * 64;
    const float scale = 0.044194173824159216f; // 1/sqrt(512)

    const float* qbase = g_q + ((size_t)bh * 1024 + i0 + warp * 16) * 64;
    unsigned qa[8][4];
    #pragma unroll
    for (int k = 0; k < 8; k++) {
        qa[k][0] = f2tf(qbase[(g    ) * 64 + k * 8 + t    ] * scale);
        qa[k][1] = f2tf(qbase[(g + 8) * 64 + k * 8 + t    ] * scale);
        qa[k][2] = f2tf(qbase[(g    ) * 64 + k * 8 + t + 4] * scale);
        qa[k][3] = f2tf(qbase[(g + 8) * 64 + k * 8 + t + 4] * scale);
    }

    auto issue_load = [&](int ch) {
        int bufi = ch & 3;
        unsigned Kb = smem_u32 + (KS_OFF + bufi * 32 * KSTRIDE) * 4;
        unsigned Vb = smem_u32 + (VS_OFF + bufi * 32 * VSTRIDE) * 4;
        #pragma unroll
        for (int it = 0; it < 2; it++) {
            int i = tid + it * 256;
            int key = i >> 4;
            int dc = (i & 15) << 2;
            int gkey = ch * 32 + key;
            int sz = (gkey < nk) ? 16 : 0;
            cp16(Kb + (key * KSTRIDE + dc) * 4, kbase + (size_t)gkey * 64 + dc, sz);
            cp16(Vb + (key * VSTRIDE + dc) * 4, vbase + (size_t)gkey * 64 + dc, sz);
        }
        asm volatile("cp.async.commit_group;\n");
    };

    float oacc[8][4];
    #pragma unroll
    for (int n = 0; n < 8; n++)
        #pragma unroll
        for (int j = 0; j < 4; j++) oacc[n][j] = 0.f;
    float lrow0 = 0.f, lrow1 = 0.f;

    unsigned* Pw = sm + PS_OFF + warp * 768;

    issue_load(0);
    if (nchunks > 1) issue_load(1); else asm volatile("cp.async.commit_group;\n");

    for (int ch = 0; ch < nchunks; ch++) {
        const int cur = ch & 3;
        if (ch + 2 < nchunks) issue_load(ch + 2);
        else asm volatile("cp.async.commit_group;\n");
        asm volatile("cp.async.wait_group 2;\n");
        __syncthreads();

        const unsigned* Kb = sm + KS_OFF + cur * 32 * KSTRIDE;
        const unsigned* Vb = sm + VS_OFF + cur * 32 * VSTRIDE;
        const int j0 = ch * 32;

        float sc[4][4];
        #pragma unroll
        for (int n = 0; n < 4; n++)
            #pragma unroll
            for (int j = 0; j < 4; j++) sc[n][j] = 0.f;
        #pragma unroll
        for (int k = 0; k < 8; k++) {
            #pragma unroll
            for (int n = 0; n < 4; n++) {
                unsigned b0 = Kb[(n * 8 + g) * KSTRIDE + k * 8 + t    ];
                unsigned b1 = Kb[(n * 8 + g) * KSTRIDE + k * 8 + t + 4];
                mma_tf32(sc[n], qa[k][0], qa[k][1], qa[k][2], qa[k][3], b0, b1);
            }
        }

        // direct exp (scores bounded), tail cols -> 0
        float s0 = 0.f, s1 = 0.f;
        #pragma unroll
        for (int n = 0; n < 4; n++) {
            int c0 = j0 + n * 8 + 2 * t;
            bool ok0 = c0 < nk, ok1 = (c0 + 1) < nk;
            float p0 = ok0 ? __expf(sc[n][0]) : 0.f;
            float p1 = ok1 ? __expf(sc[n][1]) : 0.f;
            float p2 = ok0 ? __expf(sc[n][2]) : 0.f;
            float p3 = ok1 ? __expf(sc[n][3]) : 0.f;
            s0 += p0 + p1; s1 += p2 + p3;
            Pw[(n * 8 + 2 * t    ) * 24 + g    ] = __float_as_uint(p0);
            Pw[(n * 8 + 2 * t + 1) * 24 + g    ] = __float_as_uint(p1);
            Pw[(n * 8 + 2 * t    ) * 24 + g + 8] = __float_as_uint(p2);
            Pw[(n * 8 + 2 * t + 1) * 24 + g + 8] = __float_as_uint(p3);
        }
        lrow0 += s0;
        lrow1 += s1;
        __syncwarp();

        #pragma unroll
        for (int k = 0; k < 4; k++) {
            unsigned a0 = Pw[(k * 8 + t    ) * 24 + g    ];
            unsigned a1 = Pw[(k * 8 + t    ) * 24 + g + 8];
            unsigned a2 = Pw[(k * 8 + t + 4) * 24 + g    ];
            unsigned a3 = Pw[(k * 8 + t + 4) * 24 + g + 8];
            #pragma unroll
            for (int n = 0; n < 8; n++) {
                unsigned b0 = Vb[(k * 8 + t    ) * VSTRIDE + n * 8 + g];
                unsigned b1 = Vb[(k * 8 + t + 4) * VSTRIDE + n * 8 + g];
                mma_tf32(oacc[n], a0, a1, a2, a3, b0, b1);
            }
        }
    }

    // row sums l live per-quad: reduce across the 4 t-lanes
    lrow0 += __shfl_xor_sync(0xffffffffu, lrow0, 1);
    lrow0 += __shfl_xor_sync(0xffffffffu, lrow0, 2);
    lrow1 += __shfl_xor_sync(0xffffffffu, lrow1, 1);
    lrow1 += __shfl_xor_sync(0xffffffffu, lrow1, 2);

    float r0 = 1.0f / lrow0, r1 = 1.0f / lrow1;
    int row0 = i0 + warp * 16 + g;
    int row1 = row0 + 8;
    float* o0 = g_O + ((size_t)(b * 1024 + row0)) * 512 + h * 64;
    float* o1 = g_O + ((size_t)(b * 1024 + row1)) * 512 + h * 64;
    float s0 = 0.f, q0 = 0.f, s1 = 0.f, q1 = 0.f;
    #pragma unroll
    for (int n = 0; n < 8; n++) {
        int d = n * 8 + 2 * t;
        float v00 = oacc[n][0] * r0 + qbase[(g    ) * 64 + d    ];
        float v01 = oacc[n][1] * r0 + qbase[(g    ) * 64 + d + 1];
        float v10 = oacc[n][2] * r1 + qbase[(g + 8) * 64 + d    ];
        float v11 = oacc[n][3] * r1 + qbase[(g + 8) * 64 + d + 1];
        o0[d] = v00; o0[d + 1] = v01;
        o1[d] = v10; o1[d + 1] = v11;
        s0 += v00 + v01; q0 += v00 * v00 + v01 * v01;
        s1 += v10 + v11; q1 += v10 * v10 + v11 * v11;
    }
    s0 += __shfl_xor_sync(0xffffffffu, s0, 1);
    s0 += __shfl_xor_sync(0xffffffffu, s0, 2);
    q0 += __shfl_xor_sync(0xffffffffu, q0, 1);
    q0 += __shfl_xor_sync(0xffffffffu, q0, 2);
    s1 += __shfl_xor_sync(0xffffffffu, s1, 1);
    s1 += __shfl_xor_sync(0xffffffffu, s1, 2);
    q1 += __shfl_xor_sync(0xffffffffu, q1, 1);
    q1 += __shfl_xor_sync(0xffffffffu, q1, 2);
    if (t == 0) {
        g_part[h][b * 1024 + row0][0] = s0;
        g_part[h][b * 1024 + row0][1] = q0;
        g_part[h][b * 1024 + row1][0] = s1;
        g_part[h][b * 1024 + row1][1] = q1;
    }
}

// ---------------- LN0 stats finalize (coalesced partials) ------------------
__global__ void ln_stats()
{
    int row = blockIdx.x * 256 + threadIdx.x;
    float s = 0.f, q = 0.f;
    #pragma unroll
    for (int h = 0; h < HEADS; h++) {
        float2 p = *(const float2*)&g_part[h][row][0];
        s += p.x;
        q += p.y;
    }
    float mu = s * (1.f / 512.f);
    float var = q * (1.f / 512.f) - mu * mu;
    g_mu[row] = mu;
    g_rs[row] = rsqrtf(var + 1e-5f);
}

// ---------------- final LayerNorm: g_U -> out --------------------------------
__global__ void ln_final(const float* __restrict__ gg, const float* __restrict__ bb,
                         float* __restrict__ out)
{
    __shared__ float red[4];
    const int row = blockIdx.x, t = threadIdx.x;
    const float* p = g_U + (size_t)row * 512;
    float v[4];
    #pragma unroll
    for (int i = 0; i < 4; i++) v[i] = p[t + 128 * i];

    float s = v[0] + v[1] + v[2] + v[3];
    #pragma unroll
    for (int o = 16; o > 0; o >>= 1) s += __shfl_xor_sync(0xffffffffu, s, o);
    if ((t & 31) == 0) red[t >> 5] = s;
    __syncthreads();
    s = red[0] + red[1] + red[2] + red[3];
    float mean = s * (1.f / 512.f);
    __syncthreads();

    float ss = 0.f;
    #pragma unroll
    for (int i = 0; i < 4; i++) { float d = v[i] - mean; ss += d * d; }
    #pragma unroll
    for (int o = 16; o > 0; o >>= 1) ss += __shfl_xor_sync(0xffffffffu, ss, o);
    if ((t & 31) == 0) red[t >> 5] = ss;
    __syncthreads();
    ss = red[0] + red[1] + red[2] + red[3];
    float inv = rsqrtf(ss * (1.f / 512.f) + 1e-5f);

    #pragma unroll
    for (int i = 0; i < 4; i++) {
        int c = t + 128 * i;
        out[(size_t)row * 512 + c] = (v[i] - mean) * inv * gg[c] + bb[c];
    }
}

// ---------------- launch ----------------------------------------------------
extern "C" void kernel_launch(void* const* d_in, const int* in_sizes, int n_in,
                              void* d_out, int out_size)
{
    const float* Q    = (const float*)d_in[0];
    const float* K    = (const float*)d_in[1];
    const int*   mask = (const int*)  d_in[2];
    const float* Wq   = (const float*)d_in[3];
    const float* bq   = (const float*)d_in[4];
    const float* Wk   = (const float*)d_in[5];
    const float* bk   = (const float*)d_in[6];
    const float* Wv   = (const float*)d_in[7];
    const float* bv   = (const float*)d_in[8];
    const float* Wo   = (const float*)d_in[9];
    const float* bo   = (const float*)d_in[10];
    const float* g0   = (const float*)d_in[11];
    const float* b0   = (const float*)d_in[12];
    const float* g1   = (const float*)d_in[13];
    const float* b1   = (const float*)d_in[14];
    float* out = (float*)d_out;

    static bool attr_set = false;
    if (!attr_set) {
        cudaFuncSetAttribute(flash_attn, cudaFuncAttributeMaxDynamicSharedMemorySize,
                             SMEM_FLASH);
        cudaFuncSetAttribute(gemm128<0>, cudaFuncAttributeMaxDynamicSharedMemorySize,
                             GEMM_SMEM);
        cudaFuncSetAttribute(gemm128<1>, cudaFuncAttributeMaxDynamicSharedMemorySize,
                             GEMM_SMEM);
        attr_set = true;
    }

    compact_mask<<<BATCH, 1024>>>(mask);

    dim3 gqkv(DIM / 128, MROWS / 128, 3);   // (4, 64, 3)
    gemm128<0><<<gqkv, 256, GEMM_SMEM>>>(Q, K, Wq, bq, Wk, bk, Wv, bv);

    dim3 gf(NQ / 128, BH);                  // (8, 64)
    flash_attn<<<gf, 256, SMEM_FLASH>>>();

    ln_stats<<<MROWS / 256, 256>>>();

    dim3 go(DIM / 128, MROWS / 128, 1);     // (4, 64)
    gemm128<1><<<go, 256, GEMM_SMEM>>>(nullptr, nullptr, Wo, bo, g0, b0, nullptr, nullptr);

    ln_final<<<MROWS, 128>>>(g1, b1, out);
}

// round 14
// speedup vs baseline: 1.1955x; 1.1955x over previous
#include <cuda_runtime.h>
#include <cuda_fp16.h>
#include <math.h>

// Problem constants: B=8, NQ=NK=1024, D=512, H=8, dh=64
#define BATCH 8
#define NQ 1024
#define NK 1024
#define DIM 512
#define HEADS 8
#define DH 64
#define BH (BATCH*HEADS)          // 64
#define MROWS (BATCH*NQ)          // 8192

// ---------------- scratch ----------------
__device__ float  g_q[BH * NK * DH];     // full rows, f32
__device__ __half g_kh[BH * NK * DH];    // COMPACTED rows, fp16, [bh][key][d]
__device__ __half g_vh[BH * DH * NK];    // COMPACTED keys, fp16, TRANSPOSED [bh][d][key]
__device__ float  g_O[MROWS * DIM];
__device__ float  g_U[MROWS * DIM];
__device__ float  g_mu[MROWS];
__device__ float  g_rs[MROWS];
__device__ float  g_part[HEADS][MROWS][2];
__device__ int    g_idx[BATCH * NK];
__device__ int    g_cnt[BATCH];

// ---------------- helpers ----------------
__device__ __forceinline__ unsigned f2tf(float x) {
    unsigned u;
    asm("cvt.rna.tf32.f32 %0, %1;" : "=r"(u) : "f"(x));
    return u;
}

__device__ __forceinline__ void mma_tf32(float c[4],
                                         unsigned a0, unsigned a1, unsigned a2, unsigned a3,
                                         unsigned b0, unsigned b1)
{
    asm volatile(
        "mma.sync.aligned.m16n8k8.row.col.f32.tf32.tf32.f32 "
        "{%0,%1,%2,%3}, {%4,%5,%6,%7}, {%8,%9}, {%0,%1,%2,%3};\n"
        : "+f"(c[0]), "+f"(c[1]), "+f"(c[2]), "+f"(c[3])
        : "r"(a0), "r"(a1), "r"(a2), "r"(a3), "r"(b0), "r"(b1));
}

__device__ __forceinline__ void mma_f16(float c[4],
                                        unsigned a0, unsigned a1, unsigned a2, unsigned a3,
                                        unsigned b0, unsigned b1)
{
    asm volatile(
        "mma.sync.aligned.m16n8k16.row.col.f32.f16.f16.f32 "
        "{%0,%1,%2,%3}, {%4,%5,%6,%7}, {%8,%9}, {%0,%1,%2,%3};\n"
        : "+f"(c[0]), "+f"(c[1]), "+f"(c[2]), "+f"(c[3])
        : "r"(a0), "r"(a1), "r"(a2), "r"(a3), "r"(b0), "r"(b1));
}

__device__ __forceinline__ unsigned pack_h2(float a, float b) {
    __half2 h = __floats2half2_rn(a, b);
    return *(unsigned*)&h;
}

__device__ __forceinline__ void cp16(unsigned smem_addr, const void* gptr, int src_sz) {
    asm volatile("cp.async.cg.shared.global [%0], [%1], 16, %2;\n"
                 :: "r"(smem_addr), "l"(gptr), "r"(src_sz));
}
__device__ __forceinline__ void cp16f(unsigned smem_addr, const void* gptr) {
    asm volatile("cp.async.cg.shared.global [%0], [%1], 16;\n"
                 :: "r"(smem_addr), "l"(gptr));
}

__device__ __forceinline__ unsigned smem_cast(const void* p) {
    unsigned long long q;
    asm("cvta.to.shared.u64 %0, %1;" : "=l"(q) : "l"(p));
    return (unsigned)q;
}

// ---------------- mask compaction ----------------
__global__ void compact_mask(const int* __restrict__ mask)
{
    __shared__ int warpsums[32];
    const int b = blockIdx.x, t = threadIdx.x;
    const int lane = t & 31, warp = t >> 5;
    int m = (mask[b * 1024 + t] != 0) ? 1 : 0;
    unsigned bal = __ballot_sync(0xffffffffu, m);
    int pre = __popc(bal & ((1u << lane) - 1u));
    if (lane == 0) warpsums[warp] = __popc(bal);
    __syncthreads();
    if (warp == 0) {
        int v = warpsums[lane];
        #pragma unroll
        for (int o = 1; o < 32; o <<= 1) {
            int u = __shfl_up_sync(0xffffffffu, v, o);
            if (lane >= o) v += u;
        }
        warpsums[lane] = v;
    }
    __syncthreads();
    int base = (warp == 0) ? 0 : warpsums[warp - 1];
    if (m) g_idx[b * 1024 + base + pre] = t;
    if (t == 1023) g_cnt[b] = warpsums[31];
}

// ---------------- 128x128 tensor-core GEMM (4-stage cp.async, tf32) --------
// MODE 0 (grid.z=3): z=0: Q@Wq+bq -> g_q (f32)
//                    z=1: K@Wk+bk -> g_kh (fp16, compacted, [bh][key][d])
//                    z=2: K@Wv+bv -> g_vh (fp16, compacted, TRANSPOSED [bh][d][key])
// MODE 1 (grid.z=1): A = LN0(g_O) on the fly; g_U = LN0(g_O) + relu(A@W+bias)
#define ASTRIDE 20
#define BSTRIDE 132
#define GSTAGES 4
#define GEMM_SMEM ((GSTAGES*128*ASTRIDE + GSTAGES*16*BSTRIDE) * 4)
template<int MODE>
__global__ void __launch_bounds__(256, 2) gemm128(
    const float* __restrict__ p0, const float* __restrict__ p1,
    const float* __restrict__ p2, const float* __restrict__ p3,
    const float* __restrict__ p4, const float* __restrict__ p5,
    const float* __restrict__ p6, const float* __restrict__ p7)
{
    extern __shared__ float smg[];
    float (*As)[128][ASTRIDE] = (float(*)[128][ASTRIDE])smg;
    float (*Bs)[16][BSTRIDE]  = (float(*)[16][BSTRIDE])(smg + GSTAGES*128*ASTRIDE);
    const int z = blockIdx.z;
    const int n0 = blockIdx.x * 128;
    const int bb = blockIdx.y >> 3;
    const int tyl = blockIdx.y & 7;
    const int m0 = blockIdx.y * 128;

    const float* A; const float* W; const float* bias;
    const float* gamma = p4; const float* beta = p5;
    if (MODE == 0) {
        A    = (z == 0) ? p0 : p1;
        W    = (z == 0) ? p2 : (z == 1) ? p4 : p6;
        bias = (z == 0) ? p3 : (z == 1) ? p5 : p7;
    } else {
        A = (const float*)g_O; W = p2; bias = p3;
    }

    int cnt = 1024;
    if (MODE == 0 && z > 0) {
        cnt = g_cnt[bb];
        if (tyl * 128 >= cnt) return;
    }

    const int tid = threadIdx.x;
    const int warp = tid >> 5, lane = tid & 31;
    const int wm = warp >> 2, wn = warp & 3;
    const int g = lane >> 2, t = lane & 3;
    const int mbase = wm * 64;
    const int nbase = wn * 32;

    const unsigned sA = smem_cast(smg);
    const unsigned sB = sA + (unsigned)(GSTAGES*128*ASTRIDE) * 4;

    const int r1 = tid >> 2;
    const int c4 = (tid & 3) << 2;
    const float* arow1; const float* arow2;
    float mu1 = 0.f, rs1 = 0.f, mu2 = 0.f, rs2 = 0.f;
    {
        int li1 = tyl * 128 + r1;
        int li2 = li1 + 64;
        if (MODE == 0 && z > 0) {
            int gi1 = (li1 < cnt) ? g_idx[bb * 1024 + li1] : 0;
            int gi2 = (li2 < cnt) ? g_idx[bb * 1024 + li2] : 0;
            arow1 = A + ((size_t)bb * 1024 + gi1) * 512;
            arow2 = A + ((size_t)bb * 1024 + gi2) * 512;
        } else {
            arow1 = A + ((size_t)bb * 1024 + li1) * 512;
            arow2 = A + ((size_t)bb * 1024 + li2) * 512;
        }
        if (MODE == 1) {
            mu1 = g_mu[m0 + r1];      rs1 = g_rs[m0 + r1];
            mu2 = g_mu[m0 + r1 + 64]; rs2 = g_rs[m0 + r1 + 64];
        }
    }

    auto loadAB = [&](int k0, int bufi) {
        unsigned abase = sA + (unsigned)(bufi * 128 * ASTRIDE) * 4;
        if (MODE == 0) {
            cp16f(abase + (unsigned)((r1      ) * ASTRIDE + c4) * 4, arow1 + k0 + c4);
            cp16f(abase + (unsigned)((r1 + 64 ) * ASTRIDE + c4) * 4, arow2 + k0 + c4);
        } else {
            float4 a1 = *(const float4*)(arow1 + k0 + c4);
            float4 a2 = *(const float4*)(arow2 + k0 + c4);
            float4 gm = *(const float4*)(gamma + k0 + c4);
            float4 bt = *(const float4*)(beta  + k0 + c4);
            a1.x = (a1.x - mu1) * rs1 * gm.x + bt.x;
            a1.y = (a1.y - mu1) * rs1 * gm.y + bt.y;
            a1.z = (a1.z - mu1) * rs1 * gm.z + bt.z;
            a1.w = (a1.w - mu1) * rs1 * gm.w + bt.w;
            a2.x = (a2.x - mu2) * rs2 * gm.x + bt.x;
            a2.y = (a2.y - mu2) * rs2 * gm.y + bt.y;
            a2.z = (a2.z - mu2) * rs2 * gm.z + bt.z;
            a2.w = (a2.w - mu2) * rs2 * gm.w + bt.w;
            uint4 u1 = make_uint4(f2tf(a1.x), f2tf(a1.y), f2tf(a1.z), f2tf(a1.w));
            uint4 u2 = make_uint4(f2tf(a2.x), f2tf(a2.y), f2tf(a2.z), f2tf(a2.w));
            *(uint4*)&As[bufi][r1     ][c4] = u1;
            *(uint4*)&As[bufi][r1 + 64][c4] = u2;
        }
        unsigned bbase = sB + (unsigned)(bufi * 16 * BSTRIDE) * 4;
        #pragma unroll
        for (int it = 0; it < 2; it++) {
            int idx = tid + it * 256;
            int r = idx >> 5, cc = (idx & 31) << 2;
            cp16f(bbase + (unsigned)(r * BSTRIDE + cc) * 4,
                  W + (size_t)(k0 + r) * 512 + n0 + cc);
        }
        asm volatile("cp.async.commit_group;\n");
    };

    float acc[4][4][4];
    #pragma unroll
    for (int i = 0; i < 4; i++)
        #pragma unroll
        for (int j = 0; j < 4; j++)
            #pragma unroll
            for (int q = 0; q < 4; q++) acc[i][j][q] = 0.f;

    loadAB(0, 0);
    loadAB(16, 1);

    for (int it = 0; it < 32; it++) {
        int cur = it & 3;
        if (it + 2 < 32) loadAB((it + 2) * 16, (it + 2) & 3);
        else asm volatile("cp.async.commit_group;\n");
        asm volatile("cp.async.wait_group 2;\n");
        __syncthreads();

        const unsigned* Ab = (const unsigned*)As[cur];
        const unsigned* Bb = (const unsigned*)Bs[cur];
        #pragma unroll
        for (int ks = 0; ks < 2; ks++) {
            int kk = ks * 8;
            unsigned av[4][4], bv[4][2];
            #pragma unroll
            for (int i = 0; i < 4; i++) {
                int mb = mbase + i * 16;
                av[i][0] = Ab[(mb + g    ) * ASTRIDE + kk + t    ];
                av[i][1] = Ab[(mb + g + 8) * ASTRIDE + kk + t    ];
                av[i][2] = Ab[(mb + g    ) * ASTRIDE + kk + t + 4];
                av[i][3] = Ab[(mb + g + 8) * ASTRIDE + kk + t + 4];
            }
            #pragma unroll
            for (int j = 0; j < 4; j++) {
                bv[j][0] = Bb[(kk + t    ) * BSTRIDE + nbase + j * 8 + g];
                bv[j][1] = Bb[(kk + t + 4) * BSTRIDE + nbase + j * 8 + g];
            }
            #pragma unroll
            for (int i = 0; i < 4; i++)
                #pragma unroll
                for (int j = 0; j < 4; j++)
                    mma_tf32(acc[i][j], av[i][0], av[i][1], av[i][2], av[i][3],
                             bv[j][0], bv[j][1]);
        }
    }

    #pragma unroll
    for (int i = 0; i < 4; i++) {
        int lr0 = mbase + i * 16 + g;
        #pragma unroll
        for (int j = 0; j < 4; j++) {
            int c0 = n0 + nbase + j * 8 + 2 * t;
            #pragma unroll
            for (int q = 0; q < 4; q++) {
                int lr = lr0 + (q >> 1) * 8;
                int c  = c0 + (q & 1);
                float val = acc[i][j][q] + bias[c];
                if (MODE == 0) {
                    int n = tyl * 128 + lr;
                    int h = c >> 6, d = c & 63;
                    size_t bhn = (size_t)(bb * HEADS + h);
                    if (z == 0)
                        g_q[(bhn * 1024 + n) * 64 + d] = val;
                    else if (z == 1)
                        g_kh[(bhn * 1024 + n) * 64 + d] = __float2half_rn(val);
                    else
                        g_vh[(bhn * 64 + d) * 1024 + n] = __float2half_rn(val);
                } else {
                    int r = m0 + lr;
                    float xv = (g_O[(size_t)r * 512 + c] - g_mu[r]) * g_rs[r]
                               * gamma[c] + beta[c];
                    g_U[(size_t)r * 512 + c] = xv + fmaxf(val, 0.f);
                }
            }
        }
    }
}

// ---------------- fused flash attention (fp16 mma, no P round-trip) --------
// K chunk smem: [key 32][d-pair 32 + pad 4] half2 words, stride 36
// V chunk smem: [d 64][key-pair 16 + pad 4] half2 words, stride 20
#define KST2 36
#define VST2 20
#define KCH_W (32*KST2)     // 1152 words
#define VCH_W (64*VST2)     // 1280 words
#define FSTAGES 4
#define KS_OFF 0
#define VS_OFF (FSTAGES*KCH_W)
#define SMEM_FLASH ((VS_OFF + FSTAGES*VCH_W) * 4)

__global__ void __launch_bounds__(256) flash_attn()
{
    extern __shared__ unsigned sm[];
    const unsigned smem_u32 = smem_cast(sm);

    const int bh = blockIdx.y;
    const int b = bh >> 3, h = bh & 7;
    const int i0 = blockIdx.x * 128;
    const int tid = threadIdx.x;
    const int warp = tid >> 5, lane = tid & 31;
    const int g = lane >> 2, t = lane & 3;

    const int nk = g_cnt[b];
    const int nchunks = (nk + 31) >> 5;
    const __half* kbase = g_kh + (size_t)bh * 1024 * 64;   // [key][d]
    const __half* vtbase = g_vh + (size_t)bh * 64 * 1024;  // [d][key]
    const float scale = 0.044194173824159216f; // 1/sqrt(512)

    // Q fragments, fp16, pre-scaled: qa[ks][0..3] covers k16 block ks of d
    const float* qbase = g_q + ((size_t)bh * 1024 + i0 + warp * 16) * 64;
    unsigned qa[4][4];
    #pragma unroll
    for (int ks = 0; ks < 4; ks++) {
        float2 x0 = *(const float2*)(qbase + (g    ) * 64 + ks * 16 + 2 * t);
        float2 x1 = *(const float2*)(qbase + (g + 8) * 64 + ks * 16 + 2 * t);
        float2 x2 = *(const float2*)(qbase + (g    ) * 64 + ks * 16 + 8 + 2 * t);
        float2 x3 = *(const float2*)(qbase + (g + 8) * 64 + ks * 16 + 8 + 2 * t);
        qa[ks][0] = pack_h2(x0.x * scale, x0.y * scale);
        qa[ks][1] = pack_h2(x1.x * scale, x1.y * scale);
        qa[ks][2] = pack_h2(x2.x * scale, x2.y * scale);
        qa[ks][3] = pack_h2(x3.x * scale, x3.y * scale);
    }

    // chunk loader: K 32 rows x 128B (8 pieces/row), V 64 rows x 64B (4 pieces/row)
    auto issue_load = [&](int ch) {
        int bufi = ch & 3;
        unsigned Kb = smem_u32 + (KS_OFF + bufi * KCH_W) * 4;
        unsigned Vb = smem_u32 + (VS_OFF + bufi * VCH_W) * 4;
        {   // K: 256 pieces, 1 per thread
            int key = tid >> 3;
            int pc = tid & 7;               // 16B = 8 halves of d
            int gkey = ch * 32 + key;
            int sz = (gkey < nk) ? 16 : 0;
            cp16(Kb + (unsigned)(key * KST2 + pc * 4) * 4,
                 kbase + (size_t)gkey * 64 + pc * 8, sz);
        }
        {   // V: 256 pieces, 1 per thread
            int d = tid >> 2;
            int pc = tid & 3;               // 16B = 8 keys
            int kstart = ch * 32 + pc * 8;
            int rem = nk - kstart;
            int sz = rem >= 8 ? 16 : (rem > 0 ? rem * 2 : 0);
            cp16(Vb + (unsigned)(d * VST2 + pc * 4) * 4,
                 vtbase + (size_t)d * 1024 + kstart, sz);
        }
        asm volatile("cp.async.commit_group;\n");
    };

    float oacc[8][4];
    #pragma unroll
    for (int n = 0; n < 8; n++)
        #pragma unroll
        for (int j = 0; j < 4; j++) oacc[n][j] = 0.f;
    float lrow0 = 0.f, lrow1 = 0.f;

    issue_load(0);
    if (nchunks > 1) issue_load(1); else asm volatile("cp.async.commit_group;\n");

    for (int ch = 0; ch < nchunks; ch++) {
        const int cur = ch & 3;
        if (ch + 2 < nchunks) issue_load(ch + 2);
        else asm volatile("cp.async.commit_group;\n");
        asm volatile("cp.async.wait_group 2;\n");
        __syncthreads();

        const unsigned* Kb = sm + KS_OFF + cur * KCH_W;
        const unsigned* Vb = sm + VS_OFF + cur * VCH_W;
        const int j0 = ch * 32;

        // S = (Q*scale) @ K^T : 4 k16-steps x 4 n-blocks
        float sc[4][4];
        #pragma unroll
        for (int n = 0; n < 4; n++)
            #pragma unroll
            for (int j = 0; j < 4; j++) sc[n][j] = 0.f;
        #pragma unroll
        for (int ks = 0; ks < 4; ks++) {
            #pragma unroll
            for (int n = 0; n < 4; n++) {
                unsigned b0 = Kb[(n * 8 + g) * KST2 + ks * 8 + t    ];
                unsigned b1 = Kb[(n * 8 + g) * KST2 + ks * 8 + 4 + t];
                mma_f16(sc[n], qa[ks][0], qa[ks][1], qa[ks][2], qa[ks][3], b0, b1);
            }
        }

        // direct exp (scores bounded); P fragments stay in registers as half2
        unsigned ph0[4], ph1[4];
        float s0 = 0.f, s1 = 0.f;
        #pragma unroll
        for (int n = 0; n < 4; n++) {
            int c0 = j0 + n * 8 + 2 * t;
            bool ok0 = c0 < nk, ok1 = (c0 + 1) < nk;
            float p0 = ok0 ? __expf(sc[n][0]) : 0.f;
            float p1 = ok1 ? __expf(sc[n][1]) : 0.f;
            float p2 = ok0 ? __expf(sc[n][2]) : 0.f;
            float p3 = ok1 ? __expf(sc[n][3]) : 0.f;
            s0 += p0 + p1; s1 += p2 + p3;
            ph0[n] = pack_h2(p0, p1);   // row g,   cols n*8+2t, +1
            ph1[n] = pack_h2(p2, p3);   // row g+8, same cols
        }
        lrow0 += s0;
        lrow1 += s1;

        // O += P @ V : 2 k16-groups (32 keys) x 8 n-blocks (64 d)
        #pragma unroll
        for (int kb = 0; kb < 2; kb++) {
            unsigned a0 = ph0[2 * kb    ];
            unsigned a1 = ph1[2 * kb    ];
            unsigned a2 = ph0[2 * kb + 1];
            unsigned a3 = ph1[2 * kb + 1];
            #pragma unroll
            for (int n = 0; n < 8; n++) {
                unsigned b0 = Vb[(n * 8 + g) * VST2 + kb * 8 + t    ];
                unsigned b1 = Vb[(n * 8 + g) * VST2 + kb * 8 + 4 + t];
                mma_f16(oacc[n], a0, a1, a2, a3, b0, b1);
            }
        }
        __syncthreads();
    }

    lrow0 += __shfl_xor_sync(0xffffffffu, lrow0, 1);
    lrow0 += __shfl_xor_sync(0xffffffffu, lrow0, 2);
    lrow1 += __shfl_xor_sync(0xffffffffu, lrow1, 1);
    lrow1 += __shfl_xor_sync(0xffffffffu, lrow1, 2);

    float r0 = 1.0f / lrow0, r1 = 1.0f / lrow1;
    int row0 = i0 + warp * 16 + g;
    int row1 = row0 + 8;
    float* o0 = g_O + ((size_t)(b * 1024 + row0)) * 512 + h * 64;
    float* o1 = g_O + ((size_t)(b * 1024 + row1)) * 512 + h * 64;
    float s0 = 0.f, q0 = 0.f, s1 = 0.f, q1 = 0.f;
    #pragma unroll
    for (int n = 0; n < 8; n++) {
        int d = n * 8 + 2 * t;
        float v00 = oacc[n][0] * r0 + qbase[(g    ) * 64 + d    ];
        float v01 = oacc[n][1] * r0 + qbase[(g    ) * 64 + d + 1];
        float v10 = oacc[n][2] * r1 + qbase[(g + 8) * 64 + d    ];
        float v11 = oacc[n][3] * r1 + qbase[(g + 8) * 64 + d + 1];
        o0[d] = v00; o0[d + 1] = v01;
        o1[d] = v10; o1[d + 1] = v11;
        s0 += v00 + v01; q0 += v00 * v00 + v01 * v01;
        s1 += v10 + v11; q1 += v10 * v10 + v11 * v11;
    }
    s0 += __shfl_xor_sync(0xffffffffu, s0, 1);
    s0 += __shfl_xor_sync(0xffffffffu, s0, 2);
    q0 += __shfl_xor_sync(0xffffffffu, q0, 1);
    q0 += __shfl_xor_sync(0xffffffffu, q0, 2);
    s1 += __shfl_xor_sync(0xffffffffu, s1, 1);
    s1 += __shfl_xor_sync(0xffffffffu, s1, 2);
    q1 += __shfl_xor_sync(0xffffffffu, q1, 1);
    q1 += __shfl_xor_sync(0xffffffffu, q1, 2);
    if (t == 0) {
        g_part[h][b * 1024 + row0][0] = s0;
        g_part[h][b * 1024 + row0][1] = q0;
        g_part[h][b * 1024 + row1][0] = s1;
        g_part[h][b * 1024 + row1][1] = q1;
    }
}

// ---------------- LN0 stats finalize ----------------------------------------
__global__ void ln_stats()
{
    int row = blockIdx.x * 256 + threadIdx.x;
    float s = 0.f, q = 0.f;
    #pragma unroll
    for (int h = 0; h < HEADS; h++) {
        float2 p = *(const float2*)&g_part[h][row][0];
        s += p.x;
        q += p.y;
    }
    float mu = s * (1.f / 512.f);
    float var = q * (1.f / 512.f) - mu * mu;
    g_mu[row] = mu;
    g_rs[row] = rsqrtf(var + 1e-5f);
}

// ---------------- final LayerNorm: g_U -> out --------------------------------
__global__ void ln_final(const float* __restrict__ gg, const float* __restrict__ bb,
                         float* __restrict__ out)
{
    __shared__ float red[4];
    const int row = blockIdx.x, t = threadIdx.x;
    const float* p = g_U + (size_t)row * 512;
    float v[4];
    #pragma unroll
    for (int i = 0; i < 4; i++) v[i] = p[t + 128 * i];

    float s = v[0] + v[1] + v[2] + v[3];
    #pragma unroll
    for (int o = 16; o > 0; o >>= 1) s += __shfl_xor_sync(0xffffffffu, s, o);
    if ((t & 31) == 0) red[t >> 5] = s;
    __syncthreads();
    s = red[0] + red[1] + red[2] + red[3];
    float mean = s * (1.f / 512.f);
    __syncthreads();

    float ss = 0.f;
    #pragma unroll
    for (int i = 0; i < 4; i++) { float d = v[i] - mean; ss += d * d; }
    #pragma unroll
    for (int o = 16; o > 0; o >>= 1) ss += __shfl_xor_sync(0xffffffffu, ss, o);
    if ((t & 31) == 0) red[t >> 5] = ss;
    __syncthreads();
    ss = red[0] + red[1] + red[2] + red[3];
    float inv = rsqrtf(ss * (1.f / 512.f) + 1e-5f);

    #pragma unroll
    for (int i = 0; i < 4; i++) {
        int c = t + 128 * i;
        out[(size_t)row * 512 + c] = (v[i] - mean) * inv * gg[c] + bb[c];
    }
}

// ---------------- launch ----------------------------------------------------
extern "C" void kernel_launch(void* const* d_in, const int* in_sizes, int n_in,
                              void* d_out, int out_size)
{
    const float* Q    = (const float*)d_in[0];
    const float* K    = (const float*)d_in[1];
    const int*   mask = (const int*)  d_in[2];
    const float* Wq   = (const float*)d_in[3];
    const float* bq   = (const float*)d_in[4];
    const float* Wk   = (const float*)d_in[5];
    const float* bk   = (const float*)d_in[6];
    const float* Wv   = (const float*)d_in[7];
    const float* bv   = (const float*)d_in[8];
    const float* Wo   = (const float*)d_in[9];
    const float* bo   = (const float*)d_in[10];
    const float* g0   = (const float*)d_in[11];
    const float* b0   = (const float*)d_in[12];
    const float* g1   = (const float*)d_in[13];
    const float* b1   = (const float*)d_in[14];
    float* out = (float*)d_out;

    static bool attr_set = false;
    if (!attr_set) {
        cudaFuncSetAttribute(flash_attn, cudaFuncAttributeMaxDynamicSharedMemorySize,
                             SMEM_FLASH);
        cudaFuncSetAttribute(gemm128<0>, cudaFuncAttributeMaxDynamicSharedMemorySize,
                             GEMM_SMEM);
        cudaFuncSetAttribute(gemm128<1>, cudaFuncAttributeMaxDynamicSharedMemorySize,
                             GEMM_SMEM);
        attr_set = true;
    }

    compact_mask<<<BATCH, 1024>>>(mask);

    dim3 gqkv(DIM / 128, MROWS / 128, 3);   // (4, 64, 3)
    gemm128<0><<<gqkv, 256, GEMM_SMEM>>>(Q, K, Wq, bq, Wk, bk, Wv, bv);

    dim3 gf(NQ / 128, BH);                  // (8, 64)
    flash_attn<<<gf, 256, SMEM_FLASH>>>();

    ln_stats<<<MROWS / 256, 256>>>();

    dim3 go(DIM / 128, MROWS / 128, 1);     // (4, 64)
    gemm128<1><<<go, 256, GEMM_SMEM>>>(nullptr, nullptr, Wo, bo, g0, b0, nullptr, nullptr);

    ln_final<<<MROWS, 128>>>(g1, b1, out);
}

// round 15
// speedup vs baseline: 1.1961x; 1.0005x over previous
#include <cuda_runtime.h>
#include <cuda_fp16.h>
#include <math.h>

// Problem constants: B=8, NQ=NK=1024, D=512, H=8, dh=64
#define BATCH 8
#define NQ 1024
#define NK 1024
#define DIM 512
#define HEADS 8
#define DH 64
#define BH (BATCH*HEADS)          // 64
#define MROWS (BATCH*NQ)          // 8192

// ---------------- scratch ----------------
__device__ float  g_q[BH * NK * DH];     // full rows, f32
__device__ __half g_kh[BH * NK * DH];    // COMPACTED rows, fp16, [bh][key][d]
__device__ __half g_vh[BH * DH * NK];    // COMPACTED keys, fp16, TRANSPOSED [bh][d][key]
__device__ float  g_O[MROWS * DIM];
__device__ float  g_U[MROWS * DIM];
__device__ float  g_mu[MROWS];
__device__ float  g_rs[MROWS];
__device__ float  g_part[HEADS][MROWS][2];
__device__ int    g_idx[BATCH * NK];
__device__ int    g_cnt[BATCH];

// ---------------- helpers ----------------
__device__ __forceinline__ unsigned f2tf(float x) {
    unsigned u;
    asm("cvt.rna.tf32.f32 %0, %1;" : "=r"(u) : "f"(x));
    return u;
}

__device__ __forceinline__ void mma_tf32(float c[4],
                                         unsigned a0, unsigned a1, unsigned a2, unsigned a3,
                                         unsigned b0, unsigned b1)
{
    asm volatile(
        "mma.sync.aligned.m16n8k8.row.col.f32.tf32.tf32.f32 "
        "{%0,%1,%2,%3}, {%4,%5,%6,%7}, {%8,%9}, {%0,%1,%2,%3};\n"
        : "+f"(c[0]), "+f"(c[1]), "+f"(c[2]), "+f"(c[3])
        : "r"(a0), "r"(a1), "r"(a2), "r"(a3), "r"(b0), "r"(b1));
}

__device__ __forceinline__ void mma_f16(float c[4],
                                        unsigned a0, unsigned a1, unsigned a2, unsigned a3,
                                        unsigned b0, unsigned b1)
{
    asm volatile(
        "mma.sync.aligned.m16n8k16.row.col.f32.f16.f16.f32 "
        "{%0,%1,%2,%3}, {%4,%5,%6,%7}, {%8,%9}, {%0,%1,%2,%3};\n"
        : "+f"(c[0]), "+f"(c[1]), "+f"(c[2]), "+f"(c[3])
        : "r"(a0), "r"(a1), "r"(a2), "r"(a3), "r"(b0), "r"(b1));
}

__device__ __forceinline__ unsigned pack_h2(float a, float b) {
    __half2 h = __floats2half2_rn(a, b);
    return *(unsigned*)&h;
}

__device__ __forceinline__ void cp16(unsigned smem_addr, const void* gptr, int src_sz) {
    asm volatile("cp.async.cg.shared.global [%0], [%1], 16, %2;\n"
                 :: "r"(smem_addr), "l"(gptr), "r"(src_sz));
}
__device__ __forceinline__ void cp16f(unsigned smem_addr, const void* gptr) {
    asm volatile("cp.async.cg.shared.global [%0], [%1], 16;\n"
                 :: "r"(smem_addr), "l"(gptr));
}

__device__ __forceinline__ unsigned smem_cast(const void* p) {
    unsigned long long q;
    asm("cvta.to.shared.u64 %0, %1;" : "=l"(q) : "l"(p));
    return (unsigned)q;
}

// ---------------- mask compaction ----------------
__global__ void compact_mask(const int* __restrict__ mask)
{
    __shared__ int warpsums[32];
    const int b = blockIdx.x, t = threadIdx.x;
    const int lane = t & 31, warp = t >> 5;
    int m = (mask[b * 1024 + t] != 0) ? 1 : 0;
    unsigned bal = __ballot_sync(0xffffffffu, m);
    int pre = __popc(bal & ((1u << lane) - 1u));
    if (lane == 0) warpsums[warp] = __popc(bal);
    __syncthreads();
    if (warp == 0) {
        int v = warpsums[lane];
        #pragma unroll
        for (int o = 1; o < 32; o <<= 1) {
            int u = __shfl_up_sync(0xffffffffu, v, o);
            if (lane >= o) v += u;
        }
        warpsums[lane] = v;
    }
    __syncthreads();
    int base = (warp == 0) ? 0 : warpsums[warp - 1];
    if (m) g_idx[b * 1024 + base + pre] = t;
    if (t == 1023) g_cnt[b] = warpsums[31];
}

// ---------------- 128x128 tensor-core GEMM (4-stage cp.async, tf32) --------
// MODE 0 (grid.z=3): z=0: Q@Wq+bq -> g_q (f32)
//                    z=1: K@Wk+bk -> g_kh (fp16, compacted, [bh][key][d])
//                    z=2: K@Wv+bv -> g_vh (fp16, compacted, TRANSPOSED [bh][d][key])
// MODE 1 (grid.z=1): A = LN0(g_O) on the fly; g_U = LN0(g_O) + relu(A@W+bias)
#define ASTRIDE 20
#define BSTRIDE 132
#define GSTAGES 4
#define GEMM_SMEM ((GSTAGES*128*ASTRIDE + GSTAGES*16*BSTRIDE) * 4)
template<int MODE>
__global__ void __launch_bounds__(256, 2) gemm128(
    const float* __restrict__ p0, const float* __restrict__ p1,
    const float* __restrict__ p2, const float* __restrict__ p3,
    const float* __restrict__ p4, const float* __restrict__ p5,
    const float* __restrict__ p6, const float* __restrict__ p7)
{
    extern __shared__ float smg[];
    float (*As)[128][ASTRIDE] = (float(*)[128][ASTRIDE])smg;
    float (*Bs)[16][BSTRIDE]  = (float(*)[16][BSTRIDE])(smg + GSTAGES*128*ASTRIDE);
    const int z = blockIdx.z;
    const int n0 = blockIdx.x * 128;
    const int bb = blockIdx.y >> 3;
    const int tyl = blockIdx.y & 7;
    const int m0 = blockIdx.y * 128;

    const float* A; const float* W; const float* bias;
    const float* gamma = p4; const float* beta = p5;
    if (MODE == 0) {
        A    = (z == 0) ? p0 : p1;
        W    = (z == 0) ? p2 : (z == 1) ? p4 : p6;
        bias = (z == 0) ? p3 : (z == 1) ? p5 : p7;
    } else {
        A = (const float*)g_O; W = p2; bias = p3;
    }

    int cnt = 1024;
    if (MODE == 0 && z > 0) {
        cnt = g_cnt[bb];
        if (tyl * 128 >= cnt) return;
    }

    const int tid = threadIdx.x;
    const int warp = tid >> 5, lane = tid & 31;
    const int wm = warp >> 2, wn = warp & 3;
    const int g = lane >> 2, t = lane & 3;
    const int mbase = wm * 64;
    const int nbase = wn * 32;

    const unsigned sA = smem_cast(smg);
    const unsigned sB = sA + (unsigned)(GSTAGES*128*ASTRIDE) * 4;

    const int r1 = tid >> 2;
    const int c4 = (tid & 3) << 2;
    const float* arow1; const float* arow2;
    float mu1 = 0.f, rs1 = 0.f, mu2 = 0.f, rs2 = 0.f;
    {
        int li1 = tyl * 128 + r1;
        int li2 = li1 + 64;
        if (MODE == 0 && z > 0) {
            int gi1 = (li1 < cnt) ? g_idx[bb * 1024 + li1] : 0;
            int gi2 = (li2 < cnt) ? g_idx[bb * 1024 + li2] : 0;
            arow1 = A + ((size_t)bb * 1024 + gi1) * 512;
            arow2 = A + ((size_t)bb * 1024 + gi2) * 512;
        } else {
            arow1 = A + ((size_t)bb * 1024 + li1) * 512;
            arow2 = A + ((size_t)bb * 1024 + li2) * 512;
        }
        if (MODE == 1) {
            mu1 = g_mu[m0 + r1];      rs1 = g_rs[m0 + r1];
            mu2 = g_mu[m0 + r1 + 64]; rs2 = g_rs[m0 + r1 + 64];
        }
    }

    auto loadAB = [&](int k0, int bufi) {
        unsigned abase = sA + (unsigned)(bufi * 128 * ASTRIDE) * 4;
        if (MODE == 0) {
            cp16f(abase + (unsigned)((r1      ) * ASTRIDE + c4) * 4, arow1 + k0 + c4);
            cp16f(abase + (unsigned)((r1 + 64 ) * ASTRIDE + c4) * 4, arow2 + k0 + c4);
        } else {
            float4 a1 = *(const float4*)(arow1 + k0 + c4);
            float4 a2 = *(const float4*)(arow2 + k0 + c4);
            float4 gm = *(const float4*)(gamma + k0 + c4);
            float4 bt = *(const float4*)(beta  + k0 + c4);
            a1.x = (a1.x - mu1) * rs1 * gm.x + bt.x;
            a1.y = (a1.y - mu1) * rs1 * gm.y + bt.y;
            a1.z = (a1.z - mu1) * rs1 * gm.z + bt.z;
            a1.w = (a1.w - mu1) * rs1 * gm.w + bt.w;
            a2.x = (a2.x - mu2) * rs2 * gm.x + bt.x;
            a2.y = (a2.y - mu2) * rs2 * gm.y + bt.y;
            a2.z = (a2.z - mu2) * rs2 * gm.z + bt.z;
            a2.w = (a2.w - mu2) * rs2 * gm.w + bt.w;
            uint4 u1 = make_uint4(f2tf(a1.x), f2tf(a1.y), f2tf(a1.z), f2tf(a1.w));
            uint4 u2 = make_uint4(f2tf(a2.x), f2tf(a2.y), f2tf(a2.z), f2tf(a2.w));
            *(uint4*)&As[bufi][r1     ][c4] = u1;
            *(uint4*)&As[bufi][r1 + 64][c4] = u2;
        }
        unsigned bbase = sB + (unsigned)(bufi * 16 * BSTRIDE) * 4;
        #pragma unroll
        for (int it = 0; it < 2; it++) {
            int idx = tid + it * 256;
            int r = idx >> 5, cc = (idx & 31) << 2;
            cp16f(bbase + (unsigned)(r * BSTRIDE + cc) * 4,
                  W + (size_t)(k0 + r) * 512 + n0 + cc);
        }
        asm volatile("cp.async.commit_group;\n");
    };

    float acc[4][4][4];
    #pragma unroll
    for (int i = 0; i < 4; i++)
        #pragma unroll
        for (int j = 0; j < 4; j++)
            #pragma unroll
            for (int q = 0; q < 4; q++) acc[i][j][q] = 0.f;

    loadAB(0, 0);
    loadAB(16, 1);

    for (int it = 0; it < 32; it++) {
        int cur = it & 3;
        if (it + 2 < 32) loadAB((it + 2) * 16, (it + 2) & 3);
        else asm volatile("cp.async.commit_group;\n");
        asm volatile("cp.async.wait_group 2;\n");
        __syncthreads();

        const unsigned* Ab = (const unsigned*)As[cur];
        const unsigned* Bb = (const unsigned*)Bs[cur];
        #pragma unroll
        for (int ks = 0; ks < 2; ks++) {
            int kk = ks * 8;
            unsigned av[4][4], bv[4][2];
            #pragma unroll
            for (int i = 0; i < 4; i++) {
                int mb = mbase + i * 16;
                av[i][0] = Ab[(mb + g    ) * ASTRIDE + kk + t    ];
                av[i][1] = Ab[(mb + g + 8) * ASTRIDE + kk + t    ];
                av[i][2] = Ab[(mb + g    ) * ASTRIDE + kk + t + 4];
                av[i][3] = Ab[(mb + g + 8) * ASTRIDE + kk + t + 4];
            }
            #pragma unroll
            for (int j = 0; j < 4; j++) {
                bv[j][0] = Bb[(kk + t    ) * BSTRIDE + nbase + j * 8 + g];
                bv[j][1] = Bb[(kk + t + 4) * BSTRIDE + nbase + j * 8 + g];
            }
            #pragma unroll
            for (int i = 0; i < 4; i++)
                #pragma unroll
                for (int j = 0; j < 4; j++)
                    mma_tf32(acc[i][j], av[i][0], av[i][1], av[i][2], av[i][3],
                             bv[j][0], bv[j][1]);
        }
    }

    #pragma unroll
    for (int i = 0; i < 4; i++) {
        int lr0 = mbase + i * 16 + g;
        #pragma unroll
        for (int j = 0; j < 4; j++) {
            int c0 = n0 + nbase + j * 8 + 2 * t;
            #pragma unroll
            for (int q = 0; q < 4; q++) {
                int lr = lr0 + (q >> 1) * 8;
                int c  = c0 + (q & 1);
                float val = acc[i][j][q] + bias[c];
                if (MODE == 0) {
                    int n = tyl * 128 + lr;
                    int h = c >> 6, d = c & 63;
                    size_t bhn = (size_t)(bb * HEADS + h);
                    if (z == 0)
                        g_q[(bhn * 1024 + n) * 64 + d] = val;
                    else if (z == 1)
                        g_kh[(bhn * 1024 + n) * 64 + d] = __float2half_rn(val);
                    else
                        g_vh[(bhn * 64 + d) * 1024 + n] = __float2half_rn(val);
                } else {
                    int r = m0 + lr;
                    float xv = (g_O[(size_t)r * 512 + c] - g_mu[r]) * g_rs[r]
                               * gamma[c] + beta[c];
                    g_U[(size_t)r * 512 + c] = xv + fmaxf(val, 0.f);
                }
            }
        }
    }
}

// ---------------- fused flash attention (fp16 mma, no P round-trip) --------
// K chunk smem: [key 32][d-pair 32 + pad 4] half2 words, stride 36
// V chunk smem: [d 64][key-pair 16 + pad 4] half2 words, stride 20
#define KST2 36
#define VST2 20
#define KCH_W (32*KST2)     // 1152 words
#define VCH_W (64*VST2)     // 1280 words
#define FSTAGES 4
#define KS_OFF 0
#define VS_OFF (FSTAGES*KCH_W)
#define SMEM_FLASH ((VS_OFF + FSTAGES*VCH_W) * 4)

__global__ void __launch_bounds__(256) flash_attn()
{
    extern __shared__ unsigned sm[];
    const unsigned smem_u32 = smem_cast(sm);

    const int bh = blockIdx.y;
    const int b = bh >> 3, h = bh & 7;
    const int i0 = blockIdx.x * 128;
    const int tid = threadIdx.x;
    const int warp = tid >> 5, lane = tid & 31;
    const int g = lane >> 2, t = lane & 3;

    const int nk = g_cnt[b];
    const int nchunks = (nk + 31) >> 5;
    const __half* kbase = g_kh + (size_t)bh * 1024 * 64;   // [key][d]
    const __half* vtbase = g_vh + (size_t)bh * 64 * 1024;  // [d][key]
    const float scale = 0.044194173824159216f; // 1/sqrt(512)

    // Q fragments, fp16, pre-scaled: qa[ks][0..3] covers k16 block ks of d
    const float* qbase = g_q + ((size_t)bh * 1024 + i0 + warp * 16) * 64;
    unsigned qa[4][4];
    #pragma unroll
    for (int ks = 0; ks < 4; ks++) {
        float2 x0 = *(const float2*)(qbase + (g    ) * 64 + ks * 16 + 2 * t);
        float2 x1 = *(const float2*)(qbase + (g + 8) * 64 + ks * 16 + 2 * t);
        float2 x2 = *(const float2*)(qbase + (g    ) * 64 + ks * 16 + 8 + 2 * t);
        float2 x3 = *(const float2*)(qbase + (g + 8) * 64 + ks * 16 + 8 + 2 * t);
        qa[ks][0] = pack_h2(x0.x * scale, x0.y * scale);
        qa[ks][1] = pack_h2(x1.x * scale, x1.y * scale);
        qa[ks][2] = pack_h2(x2.x * scale, x2.y * scale);
        qa[ks][3] = pack_h2(x3.x * scale, x3.y * scale);
    }

    // chunk loader: K 32 rows x 128B (8 pieces/row), V 64 rows x 64B (4 pieces/row)
    auto issue_load = [&](int ch) {
        int bufi = ch & 3;
        unsigned Kb = smem_u32 + (KS_OFF + bufi * KCH_W) * 4;
        unsigned Vb = smem_u32 + (VS_OFF + bufi * VCH_W) * 4;
        {   // K: 256 pieces, 1 per thread
            int key = tid >> 3;
            int pc = tid & 7;               // 16B = 8 halves of d
            int gkey = ch * 32 + key;
            int sz = (gkey < nk) ? 16 : 0;
            cp16(Kb + (unsigned)(key * KST2 + pc * 4) * 4,
                 kbase + (size_t)gkey * 64 + pc * 8, sz);
        }
        {   // V: 256 pieces, 1 per thread
            int d = tid >> 2;
            int pc = tid & 3;               // 16B = 8 keys
            int kstart = ch * 32 + pc * 8;
            int rem = nk - kstart;
            int sz = rem >= 8 ? 16 : (rem > 0 ? rem * 2 : 0);
            cp16(Vb + (unsigned)(d * VST2 + pc * 4) * 4,
                 vtbase + (size_t)d * 1024 + kstart, sz);
        }
        asm volatile("cp.async.commit_group;\n");
    };

    float oacc[8][4];
    #pragma unroll
    for (int n = 0; n < 8; n++)
        #pragma unroll
        for (int j = 0; j < 4; j++) oacc[n][j] = 0.f;
    float lrow0 = 0.f, lrow1 = 0.f;

    issue_load(0);
    if (nchunks > 1) issue_load(1); else asm volatile("cp.async.commit_group;\n");

    for (int ch = 0; ch < nchunks; ch++) {
        const int cur = ch & 3;
        if (ch + 2 < nchunks) issue_load(ch + 2);
        else asm volatile("cp.async.commit_group;\n");
        asm volatile("cp.async.wait_group 2;\n");
        __syncthreads();

        const unsigned* Kb = sm + KS_OFF + cur * KCH_W;
        const unsigned* Vb = sm + VS_OFF + cur * VCH_W;
        const int j0 = ch * 32;

        // S = (Q*scale) @ K^T : 4 k16-steps x 4 n-blocks
        float sc[4][4];
        #pragma unroll
        for (int n = 0; n < 4; n++)
            #pragma unroll
            for (int j = 0; j < 4; j++) sc[n][j] = 0.f;
        #pragma unroll
        for (int ks = 0; ks < 4; ks++) {
            #pragma unroll
            for (int n = 0; n < 4; n++) {
                unsigned b0 = Kb[(n * 8 + g) * KST2 + ks * 8 + t    ];
                unsigned b1 = Kb[(n * 8 + g) * KST2 + ks * 8 + 4 + t];
                mma_f16(sc[n], qa[ks][0], qa[ks][1], qa[ks][2], qa[ks][3], b0, b1);
            }
        }

        // direct exp (scores bounded); P fragments stay in registers as half2
        unsigned ph0[4], ph1[4];
        float s0 = 0.f, s1 = 0.f;
        #pragma unroll
        for (int n = 0; n < 4; n++) {
            int c0 = j0 + n * 8 + 2 * t;
            bool ok0 = c0 < nk, ok1 = (c0 + 1) < nk;
            float p0 = ok0 ? __expf(sc[n][0]) : 0.f;
            float p1 = ok1 ? __expf(sc[n][1]) : 0.f;
            float p2 = ok0 ? __expf(sc[n][2]) : 0.f;
            float p3 = ok1 ? __expf(sc[n][3]) : 0.f;
            s0 += p0 + p1; s1 += p2 + p3;
            ph0[n] = pack_h2(p0, p1);   // row g,   cols n*8+2t, +1
            ph1[n] = pack_h2(p2, p3);   // row g+8, same cols
        }
        lrow0 += s0;
        lrow1 += s1;

        // O += P @ V : 2 k16-groups (32 keys) x 8 n-blocks (64 d)
        #pragma unroll
        for (int kb = 0; kb < 2; kb++) {
            unsigned a0 = ph0[2 * kb    ];
            unsigned a1 = ph1[2 * kb    ];
            unsigned a2 = ph0[2 * kb + 1];
            unsigned a3 = ph1[2 * kb + 1];
            #pragma unroll
            for (int n = 0; n < 8; n++) {
                unsigned b0 = Vb[(n * 8 + g) * VST2 + kb * 8 + t    ];
                unsigned b1 = Vb[(n * 8 + g) * VST2 + kb * 8 + 4 + t];
                mma_f16(oacc[n], a0, a1, a2, a3, b0, b1);
            }
        }
        __syncthreads();
    }

    lrow0 += __shfl_xor_sync(0xffffffffu, lrow0, 1);
    lrow0 += __shfl_xor_sync(0xffffffffu, lrow0, 2);
    lrow1 += __shfl_xor_sync(0xffffffffu, lrow1, 1);
    lrow1 += __shfl_xor_sync(0xffffffffu, lrow1, 2);

    float r0 = 1.0f / lrow0, r1 = 1.0f / lrow1;
    int row0 = i0 + warp * 16 + g;
    int row1 = row0 + 8;
    float* o0 = g_O + ((size_t)(b * 1024 + row0)) * 512 + h * 64;
    float* o1 = g_O + ((size_t)(b * 1024 + row1)) * 512 + h * 64;
    float s0 = 0.f, q0 = 0.f, s1 = 0.f, q1 = 0.f;
    #pragma unroll
    for (int n = 0; n < 8; n++) {
        int d = n * 8 + 2 * t;
        float v00 = oacc[n][0] * r0 + qbase[(g    ) * 64 + d    ];
        float v01 = oacc[n][1] * r0 + qbase[(g    ) * 64 + d + 1];
        float v10 = oacc[n][2] * r1 + qbase[(g + 8) * 64 + d    ];
        float v11 = oacc[n][3] * r1 + qbase[(g + 8) * 64 + d + 1];
        o0[d] = v00; o0[d + 1] = v01;
        o1[d] = v10; o1[d + 1] = v11;
        s0 += v00 + v01; q0 += v00 * v00 + v01 * v01;
        s1 += v10 + v11; q1 += v10 * v10 + v11 * v11;
    }
    s0 += __shfl_xor_sync(0xffffffffu, s0, 1);
    s0 += __shfl_xor_sync(0xffffffffu, s0, 2);
    q0 += __shfl_xor_sync(0xffffffffu, q0, 1);
    q0 += __shfl_xor_sync(0xffffffffu, q0, 2);
    s1 += __shfl_xor_sync(0xffffffffu, s1, 1);
    s1 += __shfl_xor_sync(0xffffffffu, s1, 2);
    q1 += __shfl_xor_sync(0xffffffffu, q1, 1);
    q1 += __shfl_xor_sync(0xffffffffu, q1, 2);
    if (t == 0) {
        g_part[h][b * 1024 + row0][0] = s0;
        g_part[h][b * 1024 + row0][1] = q0;
        g_part[h][b * 1024 + row1][0] = s1;
        g_part[h][b * 1024 + row1][1] = q1;
    }
}

// ---------------- LN0 stats finalize ----------------------------------------
__global__ void ln_stats()
{
    int row = blockIdx.x * 256 + threadIdx.x;
    float s = 0.f, q = 0.f;
    #pragma unroll
    for (int h = 0; h < HEADS; h++) {
        float2 p = *(const float2*)&g_part[h][row][0];
        s += p.x;
        q += p.y;
    }
    float mu = s * (1.f / 512.f);
    float var = q * (1.f / 512.f) - mu * mu;
    g_mu[row] = mu;
    g_rs[row] = rsqrtf(var + 1e-5f);
}

// ---------------- final LayerNorm: g_U -> out --------------------------------
__global__ void ln_final(const float* __restrict__ gg, const float* __restrict__ bb,
                         float* __restrict__ out)
{
    __shared__ float red[4];
    const int row = blockIdx.x, t = threadIdx.x;
    const float* p = g_U + (size_t)row * 512;
    float v[4];
    #pragma unroll
    for (int i = 0; i < 4; i++) v[i] = p[t + 128 * i];

    float s = v[0] + v[1] + v[2] + v[3];
    #pragma unroll
    for (int o = 16; o > 0; o >>= 1) s += __shfl_xor_sync(0xffffffffu, s, o);
    if ((t & 31) == 0) red[t >> 5] = s;
    __syncthreads();
    s = red[0] + red[1] + red[2] + red[3];
    float mean = s * (1.f / 512.f);
    __syncthreads();

    float ss = 0.f;
    #pragma unroll
    for (int i = 0; i < 4; i++) { float d = v[i] - mean; ss += d * d; }
    #pragma unroll
    for (int o = 16; o > 0; o >>= 1) ss += __shfl_xor_sync(0xffffffffu, ss, o);
    if ((t & 31) == 0) red[t >> 5] = ss;
    __syncthreads();
    ss = red[0] + red[1] + red[2] + red[3];
    float inv = rsqrtf(ss * (1.f / 512.f) + 1e-5f);

    #pragma unroll
    for (int i = 0; i < 4; i++) {
        int c = t + 128 * i;
        out[(size_t)row * 512 + c] = (v[i] - mean) * inv * gg[c] + bb[c];
    }
}

// ---------------- launch ----------------------------------------------------
extern "C" void kernel_launch(void* const* d_in, const int* in_sizes, int n_in,
                              void* d_out, int out_size)
{
    const float* Q    = (const float*)d_in[0];
    const float* K    = (const float*)d_in[1];
    const int*   mask = (const int*)  d_in[2];
    const float* Wq   = (const float*)d_in[3];
    const float* bq   = (const float*)d_in[4];
    const float* Wk   = (const float*)d_in[5];
    const float* bk   = (const float*)d_in[6];
    const float* Wv   = (const float*)d_in[7];
    const float* bv   = (const float*)d_in[8];
    const float* Wo   = (const float*)d_in[9];
    const float* bo   = (const float*)d_in[10];
    const float* g0   = (const float*)d_in[11];
    const float* b0   = (const float*)d_in[12];
    const float* g1   = (const float*)d_in[13];
    const float* b1   = (const float*)d_in[14];
    float* out = (float*)d_out;

    static bool attr_set = false;
    if (!attr_set) {
        cudaFuncSetAttribute(flash_attn, cudaFuncAttributeMaxDynamicSharedMemorySize,
                             SMEM_FLASH);
        cudaFuncSetAttribute(gemm128<0>, cudaFuncAttributeMaxDynamicSharedMemorySize,
                             GEMM_SMEM);
        cudaFuncSetAttribute(gemm128<1>, cudaFuncAttributeMaxDynamicSharedMemorySize,
                             GEMM_SMEM);
        attr_set = true;
    }

    compact_mask<<<BATCH, 1024>>>(mask);

    dim3 gqkv(DIM / 128, MROWS / 128, 3);   // (4, 64, 3)
    gemm128<0><<<gqkv, 256, GEMM_SMEM>>>(Q, K, Wq, bq, Wk, bk, Wv, bv);

    dim3 gf(NQ / 128, BH);                  // (8, 64)
    flash_attn<<<gf, 256, SMEM_FLASH>>>();

    ln_stats<<<MROWS / 256, 256>>>();

    dim3 go(DIM / 128, MROWS / 128, 1);     // (4, 64)
    gemm128<1><<<go, 256, GEMM_SMEM>>>(nullptr, nullptr, Wo, bo, g0, b0, nullptr, nullptr);

    ln_final<<<MROWS, 128>>>(g1, b1, out);
}

// round 16
// speedup vs baseline: 1.1977x; 1.0014x over previous
#include <cuda_runtime.h>
#include <cuda_fp16.h>
#include <math.h>

// Problem constants: B=8, NQ=NK=1024, D=512, H=8, dh=64
#define BATCH 8
#define NQ 1024
#define NK 1024
#define DIM 512
#define HEADS 8
#define DH 64
#define BH (BATCH*HEADS)          // 64
#define MROWS (BATCH*NQ)          // 8192

// ---------------- scratch ----------------
__device__ float  g_q[BH * NK * DH];     // full rows, f32
__device__ __half g_kh[BH * NK * DH];    // COMPACTED rows, fp16, [bh][key][d]
__device__ __half g_vh[BH * DH * NK];    // COMPACTED keys, fp16, TRANSPOSED [bh][d][key]
__device__ float  g_O[MROWS * DIM];
__device__ float  g_U[MROWS * DIM];
__device__ float  g_mu[MROWS];
__device__ float  g_rs[MROWS];
__device__ float  g_part[HEADS][MROWS][2];
__device__ int    g_idx[BATCH * NK];
__device__ int    g_cnt[BATCH];

// ---------------- helpers ----------------
__device__ __forceinline__ unsigned f2tf(float x) {
    unsigned u;
    asm("cvt.rna.tf32.f32 %0, %1;" : "=r"(u) : "f"(x));
    return u;
}

__device__ __forceinline__ void mma_tf32(float c[4],
                                         unsigned a0, unsigned a1, unsigned a2, unsigned a3,
                                         unsigned b0, unsigned b1)
{
    asm volatile(
        "mma.sync.aligned.m16n8k8.row.col.f32.tf32.tf32.f32 "
        "{%0,%1,%2,%3}, {%4,%5,%6,%7}, {%8,%9}, {%0,%1,%2,%3};\n"
        : "+f"(c[0]), "+f"(c[1]), "+f"(c[2]), "+f"(c[3])
        : "r"(a0), "r"(a1), "r"(a2), "r"(a3), "r"(b0), "r"(b1));
}

__device__ __forceinline__ void mma_f16(float c[4],
                                        unsigned a0, unsigned a1, unsigned a2, unsigned a3,
                                        unsigned b0, unsigned b1)
{
    asm volatile(
        "mma.sync.aligned.m16n8k16.row.col.f32.f16.f16.f32 "
        "{%0,%1,%2,%3}, {%4,%5,%6,%7}, {%8,%9}, {%0,%1,%2,%3};\n"
        : "+f"(c[0]), "+f"(c[1]), "+f"(c[2]), "+f"(c[3])
        : "r"(a0), "r"(a1), "r"(a2), "r"(a3), "r"(b0), "r"(b1));
}

__device__ __forceinline__ unsigned pack_h2(float a, float b) {
    __half2 h = __floats2half2_rn(a, b);
    return *(unsigned*)&h;
}

__device__ __forceinline__ void cp16(unsigned smem_addr, const void* gptr, int src_sz) {
    asm volatile("cp.async.cg.shared.global [%0], [%1], 16, %2;\n"
                 :: "r"(smem_addr), "l"(gptr), "r"(src_sz));
}
__device__ __forceinline__ void cp16f(unsigned smem_addr, const void* gptr) {
    asm volatile("cp.async.cg.shared.global [%0], [%1], 16;\n"
                 :: "r"(smem_addr), "l"(gptr));
}

__device__ __forceinline__ unsigned smem_cast(const void* p) {
    unsigned long long q;
    asm("cvta.to.shared.u64 %0, %1;" : "=l"(q) : "l"(p));
    return (unsigned)q;
}

// ---------------- mask compaction ----------------
__global__ void compact_mask(const int* __restrict__ mask)
{
    __shared__ int warpsums[32];
    const int b = blockIdx.x, t = threadIdx.x;
    const int lane = t & 31, warp = t >> 5;
    int m = (mask[b * 1024 + t] != 0) ? 1 : 0;
    unsigned bal = __ballot_sync(0xffffffffu, m);
    int pre = __popc(bal & ((1u << lane) - 1u));
    if (lane == 0) warpsums[warp] = __popc(bal);
    __syncthreads();
    if (warp == 0) {
        int v = warpsums[lane];
        #pragma unroll
        for (int o = 1; o < 32; o <<= 1) {
            int u = __shfl_up_sync(0xffffffffu, v, o);
            if (lane >= o) v += u;
        }
        warpsums[lane] = v;
    }
    __syncthreads();
    int base = (warp == 0) ? 0 : warpsums[warp - 1];
    if (m) g_idx[b * 1024 + base + pre] = t;
    if (t == 1023) g_cnt[b] = warpsums[31];
}

// ---------------- 128x128 tensor-core GEMM (4-stage cp.async, tf32) --------
// MODE 0 (grid.z=3): z=0: Q@Wq+bq -> g_q (f32)
//                    z=1: K@Wk+bk -> g_kh (fp16, compacted, [bh][key][d])
//                    z=2: K@Wv+bv -> g_vh (fp16, compacted, TRANSPOSED [bh][d][key])
// MODE 1 (grid.z=1): A = LN0(g_O) on the fly; g_U = LN0(g_O) + relu(A@W+bias)
#define ASTRIDE 20
#define BSTRIDE 132
#define GSTAGES 4
#define GEMM_SMEM ((GSTAGES*128*ASTRIDE + GSTAGES*16*BSTRIDE) * 4)
template<int MODE>
__global__ void __launch_bounds__(256, 2) gemm128(
    const float* __restrict__ p0, const float* __restrict__ p1,
    const float* __restrict__ p2, const float* __restrict__ p3,
    const float* __restrict__ p4, const float* __restrict__ p5,
    const float* __restrict__ p6, const float* __restrict__ p7)
{
    extern __shared__ float smg[];
    float (*As)[128][ASTRIDE] = (float(*)[128][ASTRIDE])smg;
    float (*Bs)[16][BSTRIDE]  = (float(*)[16][BSTRIDE])(smg + GSTAGES*128*ASTRIDE);
    const int z = blockIdx.z;
    const int n0 = blockIdx.x * 128;
    const int bb = blockIdx.y >> 3;
    const int tyl = blockIdx.y & 7;
    const int m0 = blockIdx.y * 128;

    const float* A; const float* W; const float* bias;
    const float* gamma = p4; const float* beta = p5;
    if (MODE == 0) {
        A    = (z == 0) ? p0 : p1;
        W    = (z == 0) ? p2 : (z == 1) ? p4 : p6;
        bias = (z == 0) ? p3 : (z == 1) ? p5 : p7;
    } else {
        A = (const float*)g_O; W = p2; bias = p3;
    }

    int cnt = 1024;
    if (MODE == 0 && z > 0) {
        cnt = g_cnt[bb];
        if (tyl * 128 >= cnt) return;
    }

    const int tid = threadIdx.x;
    const int warp = tid >> 5, lane = tid & 31;
    const int wm = warp >> 2, wn = warp & 3;
    const int g = lane >> 2, t = lane & 3;
    const int mbase = wm * 64;
    const int nbase = wn * 32;

    const unsigned sA = smem_cast(smg);
    const unsigned sB = sA + (unsigned)(GSTAGES*128*ASTRIDE) * 4;

    const int r1 = tid >> 2;
    const int c4 = (tid & 3) << 2;
    const float* arow1; const float* arow2;
    float mu1 = 0.f, rs1 = 0.f, mu2 = 0.f, rs2 = 0.f;
    {
        int li1 = tyl * 128 + r1;
        int li2 = li1 + 64;
        if (MODE == 0 && z > 0) {
            int gi1 = (li1 < cnt) ? g_idx[bb * 1024 + li1] : 0;
            int gi2 = (li2 < cnt) ? g_idx[bb * 1024 + li2] : 0;
            arow1 = A + ((size_t)bb * 1024 + gi1) * 512;
            arow2 = A + ((size_t)bb * 1024 + gi2) * 512;
        } else {
            arow1 = A + ((size_t)bb * 1024 + li1) * 512;
            arow2 = A + ((size_t)bb * 1024 + li2) * 512;
        }
        if (MODE == 1) {
            mu1 = g_mu[m0 + r1];      rs1 = g_rs[m0 + r1];
            mu2 = g_mu[m0 + r1 + 64]; rs2 = g_rs[m0 + r1 + 64];
        }
    }

    auto loadAB = [&](int k0, int bufi) {
        unsigned abase = sA + (unsigned)(bufi * 128 * ASTRIDE) * 4;
        if (MODE == 0) {
            cp16f(abase + (unsigned)((r1      ) * ASTRIDE + c4) * 4, arow1 + k0 + c4);
            cp16f(abase + (unsigned)((r1 + 64 ) * ASTRIDE + c4) * 4, arow2 + k0 + c4);
        } else {
            float4 a1 = *(const float4*)(arow1 + k0 + c4);
            float4 a2 = *(const float4*)(arow2 + k0 + c4);
            float4 gm = *(const float4*)(gamma + k0 + c4);
            float4 bt = *(const float4*)(beta  + k0 + c4);
            a1.x = (a1.x - mu1) * rs1 * gm.x + bt.x;
            a1.y = (a1.y - mu1) * rs1 * gm.y + bt.y;
            a1.z = (a1.z - mu1) * rs1 * gm.z + bt.z;
            a1.w = (a1.w - mu1) * rs1 * gm.w + bt.w;
            a2.x = (a2.x - mu2) * rs2 * gm.x + bt.x;
            a2.y = (a2.y - mu2) * rs2 * gm.y + bt.y;
            a2.z = (a2.z - mu2) * rs2 * gm.z + bt.z;
            a2.w = (a2.w - mu2) * rs2 * gm.w + bt.w;
            uint4 u1 = make_uint4(f2tf(a1.x), f2tf(a1.y), f2tf(a1.z), f2tf(a1.w));
            uint4 u2 = make_uint4(f2tf(a2.x), f2tf(a2.y), f2tf(a2.z), f2tf(a2.w));
            *(uint4*)&As[bufi][r1     ][c4] = u1;
            *(uint4*)&As[bufi][r1 + 64][c4] = u2;
        }
        unsigned bbase = sB + (unsigned)(bufi * 16 * BSTRIDE) * 4;
        #pragma unroll
        for (int it = 0; it < 2; it++) {
            int idx = tid + it * 256;
            int r = idx >> 5, cc = (idx & 31) << 2;
            cp16f(bbase + (unsigned)(r * BSTRIDE + cc) * 4,
                  W + (size_t)(k0 + r) * 512 + n0 + cc);
        }
        asm volatile("cp.async.commit_group;\n");
    };

    float acc[4][4][4];
    #pragma unroll
    for (int i = 0; i < 4; i++)
        #pragma unroll
        for (int j = 0; j < 4; j++)
            #pragma unroll
            for (int q = 0; q < 4; q++) acc[i][j][q] = 0.f;

    loadAB(0, 0);
    loadAB(16, 1);

    for (int it = 0; it < 32; it++) {
        int cur = it & 3;
        if (it + 2 < 32) loadAB((it + 2) * 16, (it + 2) & 3);
        else asm volatile("cp.async.commit_group;\n");
        asm volatile("cp.async.wait_group 2;\n");
        __syncthreads();

        const unsigned* Ab = (const unsigned*)As[cur];
        const unsigned* Bb = (const unsigned*)Bs[cur];
        #pragma unroll
        for (int ks = 0; ks < 2; ks++) {
            int kk = ks * 8;
            unsigned av[4][4], bv[4][2];
            #pragma unroll
            for (int i = 0; i < 4; i++) {
                int mb = mbase + i * 16;
                av[i][0] = Ab[(mb + g    ) * ASTRIDE + kk + t    ];
                av[i][1] = Ab[(mb + g + 8) * ASTRIDE + kk + t    ];
                av[i][2] = Ab[(mb + g    ) * ASTRIDE + kk + t + 4];
                av[i][3] = Ab[(mb + g + 8) * ASTRIDE + kk + t + 4];
            }
            #pragma unroll
            for (int j = 0; j < 4; j++) {
                bv[j][0] = Bb[(kk + t    ) * BSTRIDE + nbase + j * 8 + g];
                bv[j][1] = Bb[(kk + t + 4) * BSTRIDE + nbase + j * 8 + g];
            }
            #pragma unroll
            for (int i = 0; i < 4; i++)
                #pragma unroll
                for (int j = 0; j < 4; j++)
                    mma_tf32(acc[i][j], av[i][0], av[i][1], av[i][2], av[i][3],
                             bv[j][0], bv[j][1]);
        }
    }

    #pragma unroll
    for (int i = 0; i < 4; i++) {
        int lr0 = mbase + i * 16 + g;
        #pragma unroll
        for (int j = 0; j < 4; j++) {
            int c0 = n0 + nbase + j * 8 + 2 * t;
            #pragma unroll
            for (int q = 0; q < 4; q++) {
                int lr = lr0 + (q >> 1) * 8;
                int c  = c0 + (q & 1);
                float val = acc[i][j][q] + bias[c];
                if (MODE == 0) {
                    int n = tyl * 128 + lr;
                    int h = c >> 6, d = c & 63;
                    size_t bhn = (size_t)(bb * HEADS + h);
                    if (z == 0)
                        g_q[(bhn * 1024 + n) * 64 + d] = val;
                    else if (z == 1)
                        g_kh[(bhn * 1024 + n) * 64 + d] = __float2half_rn(val);
                    else
                        g_vh[(bhn * 64 + d) * 1024 + n] = __float2half_rn(val);
                } else {
                    int r = m0 + lr;
                    float xv = (g_O[(size_t)r * 512 + c] - g_mu[r]) * g_rs[r]
                               * gamma[c] + beta[c];
                    g_U[(size_t)r * 512 + c] = xv + fmaxf(val, 0.f);
                }
            }
        }
    }
}

// ---------------- fused flash attention (fp16 mma, no P round-trip) --------
// K chunk smem: [key 32][d-pair 32 + pad 4] half2 words, stride 36
// V chunk smem: [d 64][key-pair 16 + pad 4] half2 words, stride 20
#define KST2 36
#define VST2 20
#define KCH_W (32*KST2)     // 1152 words
#define VCH_W (64*VST2)     // 1280 words
#define FSTAGES 4
#define KS_OFF 0
#define VS_OFF (FSTAGES*KCH_W)
#define SMEM_FLASH ((VS_OFF + FSTAGES*VCH_W) * 4)

__global__ void __launch_bounds__(256) flash_attn()
{
    extern __shared__ unsigned sm[];
    const unsigned smem_u32 = smem_cast(sm);

    const int bh = blockIdx.y;
    const int b = bh >> 3, h = bh & 7;
    const int i0 = blockIdx.x * 128;
    const int tid = threadIdx.x;
    const int warp = tid >> 5, lane = tid & 31;
    const int g = lane >> 2, t = lane & 3;

    const int nk = g_cnt[b];
    const int nchunks = (nk + 31) >> 5;
    const __half* kbase = g_kh + (size_t)bh * 1024 * 64;   // [key][d]
    const __half* vtbase = g_vh + (size_t)bh * 64 * 1024;  // [d][key]
    const float scale = 0.044194173824159216f; // 1/sqrt(512)

    // Q fragments, fp16, pre-scaled: qa[ks][0..3] covers k16 block ks of d
    const float* qbase = g_q + ((size_t)bh * 1024 + i0 + warp * 16) * 64;
    unsigned qa[4][4];
    #pragma unroll
    for (int ks = 0; ks < 4; ks++) {
        float2 x0 = *(const float2*)(qbase + (g    ) * 64 + ks * 16 + 2 * t);
        float2 x1 = *(const float2*)(qbase + (g + 8) * 64 + ks * 16 + 2 * t);
        float2 x2 = *(const float2*)(qbase + (g    ) * 64 + ks * 16 + 8 + 2 * t);
        float2 x3 = *(const float2*)(qbase + (g + 8) * 64 + ks * 16 + 8 + 2 * t);
        qa[ks][0] = pack_h2(x0.x * scale, x0.y * scale);
        qa[ks][1] = pack_h2(x1.x * scale, x1.y * scale);
        qa[ks][2] = pack_h2(x2.x * scale, x2.y * scale);
        qa[ks][3] = pack_h2(x3.x * scale, x3.y * scale);
    }

    // chunk loader: K 32 rows x 128B (8 pieces/row), V 64 rows x 64B (4 pieces/row)
    auto issue_load = [&](int ch) {
        int bufi = ch & 3;
        unsigned Kb = smem_u32 + (KS_OFF + bufi * KCH_W) * 4;
        unsigned Vb = smem_u32 + (VS_OFF + bufi * VCH_W) * 4;
        {   // K: 256 pieces, 1 per thread
            int key = tid >> 3;
            int pc = tid & 7;               // 16B = 8 halves of d
            int gkey = ch * 32 + key;
            int sz = (gkey < nk) ? 16 : 0;
            cp16(Kb + (unsigned)(key * KST2 + pc * 4) * 4,
                 kbase + (size_t)gkey * 64 + pc * 8, sz);
        }
        {   // V: 256 pieces, 1 per thread
            int d = tid >> 2;
            int pc = tid & 3;               // 16B = 8 keys
            int kstart = ch * 32 + pc * 8;
            int rem = nk - kstart;
            int sz = rem >= 8 ? 16 : (rem > 0 ? rem * 2 : 0);
            cp16(Vb + (unsigned)(d * VST2 + pc * 4) * 4,
                 vtbase + (size_t)d * 1024 + kstart, sz);
        }
        asm volatile("cp.async.commit_group;\n");
    };

    float oacc[8][4];
    #pragma unroll
    for (int n = 0; n < 8; n++)
        #pragma unroll
        for (int j = 0; j < 4; j++) oacc[n][j] = 0.f;
    float lrow0 = 0.f, lrow1 = 0.f;

    issue_load(0);
    if (nchunks > 1) issue_load(1); else asm volatile("cp.async.commit_group;\n");

    for (int ch = 0; ch < nchunks; ch++) {
        const int cur = ch & 3;
        if (ch + 2 < nchunks) issue_load(ch + 2);
        else asm volatile("cp.async.commit_group;\n");
        asm volatile("cp.async.wait_group 2;\n");
        __syncthreads();

        const unsigned* Kb = sm + KS_OFF + cur * KCH_W;
        const unsigned* Vb = sm + VS_OFF + cur * VCH_W;
        const int j0 = ch * 32;

        // S = (Q*scale) @ K^T : 4 k16-steps x 4 n-blocks
        float sc[4][4];
        #pragma unroll
        for (int n = 0; n < 4; n++)
            #pragma unroll
            for (int j = 0; j < 4; j++) sc[n][j] = 0.f;
        #pragma unroll
        for (int ks = 0; ks < 4; ks++) {
            #pragma unroll
            for (int n = 0; n < 4; n++) {
                unsigned b0 = Kb[(n * 8 + g) * KST2 + ks * 8 + t    ];
                unsigned b1 = Kb[(n * 8 + g) * KST2 + ks * 8 + 4 + t];
                mma_f16(sc[n], qa[ks][0], qa[ks][1], qa[ks][2], qa[ks][3], b0, b1);
            }
        }

        // direct exp (scores bounded); P fragments stay in registers as half2
        unsigned ph0[4], ph1[4];
        float s0 = 0.f, s1 = 0.f;
        #pragma unroll
        for (int n = 0; n < 4; n++) {
            int c0 = j0 + n * 8 + 2 * t;
            bool ok0 = c0 < nk, ok1 = (c0 + 1) < nk;
            float p0 = ok0 ? __expf(sc[n][0]) : 0.f;
            float p1 = ok1 ? __expf(sc[n][1]) : 0.f;
            float p2 = ok0 ? __expf(sc[n][2]) : 0.f;
            float p3 = ok1 ? __expf(sc[n][3]) : 0.f;
            s0 += p0 + p1; s1 += p2 + p3;
            ph0[n] = pack_h2(p0, p1);   // row g,   cols n*8+2t, +1
            ph1[n] = pack_h2(p2, p3);   // row g+8, same cols
        }
        lrow0 += s0;
        lrow1 += s1;

        // O += P @ V : 2 k16-groups (32 keys) x 8 n-blocks (64 d)
        #pragma unroll
        for (int kb = 0; kb < 2; kb++) {
            unsigned a0 = ph0[2 * kb    ];
            unsigned a1 = ph1[2 * kb    ];
            unsigned a2 = ph0[2 * kb + 1];
            unsigned a3 = ph1[2 * kb + 1];
            #pragma unroll
            for (int n = 0; n < 8; n++) {
                unsigned b0 = Vb[(n * 8 + g) * VST2 + kb * 8 + t    ];
                unsigned b1 = Vb[(n * 8 + g) * VST2 + kb * 8 + 4 + t];
                mma_f16(oacc[n], a0, a1, a2, a3, b0, b1);
            }
        }
        __syncthreads();
    }

    lrow0 += __shfl_xor_sync(0xffffffffu, lrow0, 1);
    lrow0 += __shfl_xor_sync(0xffffffffu, lrow0, 2);
    lrow1 += __shfl_xor_sync(0xffffffffu, lrow1, 1);
    lrow1 += __shfl_xor_sync(0xffffffffu, lrow1, 2);

    float r0 = 1.0f / lrow0, r1 = 1.0f / lrow1;
    int row0 = i0 + warp * 16 + g;
    int row1 = row0 + 8;
    float* o0 = g_O + ((size_t)(b * 1024 + row0)) * 512 + h * 64;
    float* o1 = g_O + ((size_t)(b * 1024 + row1)) * 512 + h * 64;
    float s0 = 0.f, q0 = 0.f, s1 = 0.f, q1 = 0.f;
    #pragma unroll
    for (int n = 0; n < 8; n++) {
        int d = n * 8 + 2 * t;
        float v00 = oacc[n][0] * r0 + qbase[(g    ) * 64 + d    ];
        float v01 = oacc[n][1] * r0 + qbase[(g    ) * 64 + d + 1];
        float v10 = oacc[n][2] * r1 + qbase[(g + 8) * 64 + d    ];
        float v11 = oacc[n][3] * r1 + qbase[(g + 8) * 64 + d + 1];
        o0[d] = v00; o0[d + 1] = v01;
        o1[d] = v10; o1[d + 1] = v11;
        s0 += v00 + v01; q0 += v00 * v00 + v01 * v01;
        s1 += v10 + v11; q1 += v10 * v10 + v11 * v11;
    }
    s0 += __shfl_xor_sync(0xffffffffu, s0, 1);
    s0 += __shfl_xor_sync(0xffffffffu, s0, 2);
    q0 += __shfl_xor_sync(0xffffffffu, q0, 1);
    q0 += __shfl_xor_sync(0xffffffffu, q0, 2);
    s1 += __shfl_xor_sync(0xffffffffu, s1, 1);
    s1 += __shfl_xor_sync(0xffffffffu, s1, 2);
    q1 += __shfl_xor_sync(0xffffffffu, q1, 1);
    q1 += __shfl_xor_sync(0xffffffffu, q1, 2);
    if (t == 0) {
        g_part[h][b * 1024 + row0][0] = s0;
        g_part[h][b * 1024 + row0][1] = q0;
        g_part[h][b * 1024 + row1][0] = s1;
        g_part[h][b * 1024 + row1][1] = q1;
    }
}

// ---------------- LN0 stats finalize ----------------------------------------
__global__ void ln_stats()
{
    int row = blockIdx.x * 256 + threadIdx.x;
    float s = 0.f, q = 0.f;
    #pragma unroll
    for (int h = 0; h < HEADS; h++) {
        float2 p = *(const float2*)&g_part[h][row][0];
        s += p.x;
        q += p.y;
    }
    float mu = s * (1.f / 512.f);
    float var = q * (1.f / 512.f) - mu * mu;
    g_mu[row] = mu;
    g_rs[row] = rsqrtf(var + 1e-5f);
}

// ---------------- final LayerNorm: g_U -> out --------------------------------
__global__ void ln_final(const float* __restrict__ gg, const float* __restrict__ bb,
                         float* __restrict__ out)
{
    __shared__ float red[4];
    const int row = blockIdx.x, t = threadIdx.x;
    const float* p = g_U + (size_t)row * 512;
    float v[4];
    #pragma unroll
    for (int i = 0; i < 4; i++) v[i] = p[t + 128 * i];

    float s = v[0] + v[1] + v[2] + v[3];
    #pragma unroll
    for (int o = 16; o > 0; o >>= 1) s += __shfl_xor_sync(0xffffffffu, s, o);
    if ((t & 31) == 0) red[t >> 5] = s;
    __syncthreads();
    s = red[0] + red[1] + red[2] + red[3];
    float mean = s * (1.f / 512.f);
    __syncthreads();

    float ss = 0.f;
    #pragma unroll
    for (int i = 0; i < 4; i++) { float d = v[i] - mean; ss += d * d; }
    #pragma unroll
    for (int o = 16; o > 0; o >>= 1) ss += __shfl_xor_sync(0xffffffffu, ss, o);
    if ((t & 31) == 0) red[t >> 5] = ss;
    __syncthreads();
    ss = red[0] + red[1] + red[2] + red[3];
    float inv = rsqrtf(ss * (1.f / 512.f) + 1e-5f);

    #pragma unroll
    for (int i = 0; i < 4; i++) {
        int c = t + 128 * i;
        out[(size_t)row * 512 + c] = (v[i] - mean) * inv * gg[c] + bb[c];
    }
}

// ---------------- launch ----------------------------------------------------
extern "C" void kernel_launch(void* const* d_in, const int* in_sizes, int n_in,
                              void* d_out, int out_size)
{
    const float* Q    = (const float*)d_in[0];
    const float* K    = (const float*)d_in[1];
    const int*   mask = (const int*)  d_in[2];
    const float* Wq   = (const float*)d_in[3];
    const float* bq   = (const float*)d_in[4];
    const float* Wk   = (const float*)d_in[5];
    const float* bk   = (const float*)d_in[6];
    const float* Wv   = (const float*)d_in[7];
    const float* bv   = (const float*)d_in[8];
    const float* Wo   = (const float*)d_in[9];
    const float* bo   = (const float*)d_in[10];
    const float* g0   = (const float*)d_in[11];
    const float* b0   = (const float*)d_in[12];
    const float* g1   = (const float*)d_in[13];
    const float* b1   = (const float*)d_in[14];
    float* out = (float*)d_out;

    static bool attr_set = false;
    if (!attr_set) {
        cudaFuncSetAttribute(flash_attn, cudaFuncAttributeMaxDynamicSharedMemorySize,
                             SMEM_FLASH);
        cudaFuncSetAttribute(gemm128<0>, cudaFuncAttributeMaxDynamicSharedMemorySize,
                             GEMM_SMEM);
        cudaFuncSetAttribute(gemm128<1>, cudaFuncAttributeMaxDynamicSharedMemorySize,
                             GEMM_SMEM);
        attr_set = true;
    }

    compact_mask<<<BATCH, 1024>>>(mask);

    dim3 gqkv(DIM / 128, MROWS / 128, 3);   // (4, 64, 3)
    gemm128<0><<<gqkv, 256, GEMM_SMEM>>>(Q, K, Wq, bq, Wk, bk, Wv, bv);

    dim3 gf(NQ / 128, BH);                  // (8, 64)
    flash_attn<<<gf, 256, SMEM_FLASH>>>();

    ln_stats<<<MROWS / 256, 256>>>();

    dim3 go(DIM / 128, MROWS / 128, 1);     // (4, 64)
    gemm128<1><<<go, 256, GEMM_SMEM>>>(nullptr, nullptr, Wo, bo, g0, b0, nullptr, nullptr);

    ln_final<<<MROWS, 128>>>(g1, b1, out);
}